// round 13
// baseline (speedup 1.0000x reference)
#include <cuda_runtime.h>
#include <cuda_fp16.h>
#include <cstdint>

// Problem constants
#define Bsz   64
#define Tlen  256
#define INSZ  256
#define Hdim  64
#define Gdim  256        // 4*Hdim
#define Vocab 8000
#define Mrows (Bsz * Tlen)   // 16384

// Scratch (device globals; no allocation allowed in kernel_launch)
__device__ float g_xproj[Mrows * Gdim];
__device__ float g_h1[Mrows * Hdim];
__device__ __align__(128) __half g_Ah[Mrows * Hdim];    // h2 rounded to fp16
__device__ __align__(128) __half g_Bh[Vocab * Hdim];    // 8*Wl rounded to fp16

// ---------------- packed f32x2 helpers ----------------
__device__ __forceinline__ unsigned long long pack2(float x) {
    unsigned long long r;
    asm("mov.b64 %0, {%1, %1};" : "=l"(r) : "f"(x));
    return r;
}
__device__ __forceinline__ unsigned long long pack2v(float x, float y) {
    unsigned long long r;
    asm("mov.b64 %0, {%1, %2};" : "=l"(r) : "f"(x), "f"(y));
    return r;
}
__device__ __forceinline__ void fma2(unsigned long long& d, unsigned long long a,
                                     unsigned long long b) {
    asm("fma.rn.f32x2 %0, %1, %2, %0;" : "+l"(d) : "l"(a), "l"(b));
}
__device__ __forceinline__ float2 unpack2(unsigned long long v) {
    float2 f;
    asm("mov.b64 {%0, %1}, %2;" : "=f"(f.x), "=f"(f.y) : "l"(v));
    return f;
}
__device__ __forceinline__ float fast_rcp(float x) {
    float r;
    asm("rcp.approx.f32 %0, %1;" : "=f"(r) : "f"(x));
    return r;
}
__device__ __forceinline__ float sigmoidf_(float x) {
    return fast_rcp(1.0f + __expf(-x));
}
__device__ __forceinline__ float tanh_fast(float x) {
    return 1.0f - 2.0f * fast_rcp(1.0f + __expf(2.0f * x));
}
// 64-long dot via LDS.128: wp = 32 packed f32x2, h = 64 floats (16B-aligned SMEM).
__device__ __forceinline__ float dot64v(const unsigned long long* wp, const float* h) {
    const ulonglong2* hp = reinterpret_cast<const ulonglong2*>(h);
    unsigned long long a0 = 0ULL, a1 = 0ULL, a2 = 0ULL, a3 = 0ULL;
#pragma unroll
    for (int j = 0; j < 16; j += 2) {
        ulonglong2 h01 = hp[j];
        ulonglong2 h23 = hp[j + 1];
        fma2(a0, wp[2 * j + 0], h01.x);
        fma2(a1, wp[2 * j + 1], h01.y);
        fma2(a2, wp[2 * j + 2], h23.x);
        fma2(a3, wp[2 * j + 3], h23.y);
    }
    float2 s0 = unpack2(a0), s1 = unpack2(a1), s2 = unpack2(a2), s3 = unpack2(a3);
    return (((s0.x + s0.y) + (s1.x + s1.y)) + ((s2.x + s2.y) + (s3.x + s3.y)));
}

// ---------------- generic C[M,N] = A[M,K] * B[N,K]^T + bias1 (+bias2) ----------------
__global__ void gemm_nt_bias(const float* __restrict__ A, const float* __restrict__ Bm,
                             const float* __restrict__ bias1, const float* __restrict__ bias2,
                             float* __restrict__ C, int M, int N, int K)
{
    __shared__ __align__(16) float As[64][17];
    __shared__ __align__(16) float Bs[16][68];

    const int t  = threadIdx.x;
    const int bm = blockIdx.y * 64;
    const int bn = blockIdx.x * 64;
    const int tm = (t >> 4) << 2;
    const int tn = (t & 15) << 2;
    const int lr = t >> 2;
    const int lk = (t & 3) << 2;

    unsigned long long acc[4][2];
#pragma unroll
    for (int i = 0; i < 4; i++) { acc[i][0] = 0ULL; acc[i][1] = 0ULL; }

    const float* Aptr = A  + (size_t)(bm + lr) * K + lk;
    const float* Bptr = Bm + (size_t)(bn + lr) * K + lk;

    for (int k0 = 0; k0 < K; k0 += 16) {
        float4 av = *reinterpret_cast<const float4*>(Aptr + k0);
        float4 bv = *reinterpret_cast<const float4*>(Bptr + k0);
        As[lr][lk + 0] = av.x; As[lr][lk + 1] = av.y;
        As[lr][lk + 2] = av.z; As[lr][lk + 3] = av.w;
        Bs[lk + 0][lr] = bv.x; Bs[lk + 1][lr] = bv.y;
        Bs[lk + 2][lr] = bv.z; Bs[lk + 3][lr] = bv.w;
        __syncthreads();
#pragma unroll
        for (int kk = 0; kk < 16; kk++) {
            unsigned long long b0 =
                *reinterpret_cast<const unsigned long long*>(&Bs[kk][tn]);
            unsigned long long b1 =
                *reinterpret_cast<const unsigned long long*>(&Bs[kk][tn + 2]);
#pragma unroll
            for (int i = 0; i < 4; i++) {
                unsigned long long ap = pack2(As[tm + i][kk]);
                fma2(acc[i][0], ap, b0);
                fma2(acc[i][1], ap, b1);
            }
        }
        __syncthreads();
    }

    float4 bvec;
    bvec.x = bias1[bn + tn + 0];
    bvec.y = bias1[bn + tn + 1];
    bvec.z = bias1[bn + tn + 2];
    bvec.w = bias1[bn + tn + 3];
    if (bias2) {
        bvec.x += bias2[bn + tn + 0];
        bvec.y += bias2[bn + tn + 1];
        bvec.z += bias2[bn + tn + 2];
        bvec.w += bias2[bn + tn + 3];
    }
#pragma unroll
    for (int i = 0; i < 4; i++) {
        float2 lo = unpack2(acc[i][0]);
        float2 hi = unpack2(acc[i][1]);
        float4 v = make_float4(lo.x + bvec.x, lo.y + bvec.y,
                               hi.x + bvec.z, hi.y + bvec.w);
        *reinterpret_cast<float4*>(&C[(size_t)(bm + tm + i) * N + bn + tn]) = v;
    }
}

// ============ LSTM recurrence: quad-shuffle, one barrier, 3-deep xproj prefetch =====
__global__ void __launch_bounds__(256, 1)
lstm_layer(const float* __restrict__ xproj,   // [B,T,256] incl. biases
           const float* __restrict__ Whh,     // [256,64]
           float* __restrict__ hout,          // [B,T,64] fp32 or null
           __half* __restrict__ ah_out)       // [B,T,64] fp16 or null
{
    __shared__ __align__(16) float h_sh[2][Hdim];

    const int b = blockIdx.x;
    const int tid = threadIdx.x;
    const int q = tid >> 2;          // h index 0..63
    const int k = tid & 3;           // gate type 0=i 1=f 2=g 3=o
    const int base = (tid & 31) & ~3;
    const int gidx = k * Hdim + q;   // weight row / xproj column

    unsigned long long wp[Hdim / 2];
#pragma unroll
    for (int j = 0; j < Hdim / 2; j++) {
        float2 v = *reinterpret_cast<const float2*>(Whh + gidx * Hdim + 2 * j);
        wp[j] = pack2v(v.x, v.y);
    }

    if (tid < Hdim) { h_sh[0][tid] = 0.0f; h_sh[1][tid] = 0.0f; }
    __syncthreads();

    const float* xp = xproj + (size_t)b * Tlen * Gdim;
    // 3-deep prefetch ring: load at step t is consumed at step t+3
    float x0v = xp[gidx];
    float x1v = xp[Gdim + gidx];
    float x2v = xp[2 * Gdim + gidx];
    float c = 0.0f;

    for (int t = 0; t < Tlen; t++) {
        float val = x0v + dot64v(wp, h_sh[t & 1]);
        x0v = x1v;
        x1v = x2v;
        if (t + 3 < Tlen) x2v = xp[(size_t)(t + 3) * Gdim + gidx];

        float act = (k == 2) ? tanh_fast(val) : sigmoidf_(val);

        float iv = __shfl_sync(0xffffffffu, act, base + 0);
        float fv = __shfl_sync(0xffffffffu, act, base + 1);
        float gv = __shfl_sync(0xffffffffu, act, base + 2);
        float ov = __shfl_sync(0xffffffffu, act, base + 3);

        c = fv * c + iv * gv;
        float hn = ov * tanh_fast(c);

        if (k == 0) {
            h_sh[(t + 1) & 1][q] = hn;
            size_t idx = ((size_t)b * Tlen + t) * Hdim + q;
            if (hout) hout[idx] = hn;
            if (ah_out) ah_out[idx] = __float2half(hn);
        }
        __syncthreads();
    }
}

// ---------------- Wl -> fp16 (scaled by 8 for fp16 normal range) -------
__global__ void cvt_bh(const float* __restrict__ in, __half* __restrict__ out, int n)
{
    int i = blockIdx.x * blockDim.x + threadIdx.x;
    if (i < n) out[i] = __float2half(in[i] * 8.0f);
}

// ============ HMMA fp16 logits GEMM: paired-bn CTAs (halve A L2 re-reads) ===========
// CTA owns TWO bn columns (128 vocab cols total): B0/B1 resident (8KB each),
// A double-buffered (2 x 16KB) shared across both columns. Last CTA (x=62) has
// only one valid column (8000 = 62*128 + 64).
#define SWZ128(off) ((off) ^ (((off) >> 3) & 0x70))
#define LS_B0   0
#define LS_B1   8192
#define LS_A    16384
#define LS_ASTG 16384
#define LG_SMEM (16384 + 2 * 16384 + 1024)
#define NM_TILES 8

static __device__ __forceinline__ uint32_t smem_u32(const void* p) {
    uint32_t a;
    asm("{ .reg .u64 t; cvta.to.shared.u64 t, %1; cvt.u32.u64 %0, t; }"
        : "=r"(a) : "l"(p));
    return a;
}
__device__ __forceinline__ void cp16(uint32_t dst, const void* src) {
    asm volatile("cp.async.cg.shared.global [%0], [%1], 16;"
                 :: "r"(dst), "l"(src));
}
__device__ __forceinline__ void cp_commit() {
    asm volatile("cp.async.commit_group;" ::: "memory");
}
template <int N>
__device__ __forceinline__ void cp_wait() {
    asm volatile("cp.async.wait_group %0;" :: "n"(N) : "memory");
}
__device__ __forceinline__ void ldsm_x4(uint32_t& r0, uint32_t& r1, uint32_t& r2,
                                        uint32_t& r3, uint32_t addr) {
    asm volatile("ldmatrix.sync.aligned.m8n8.x4.shared.b16 {%0,%1,%2,%3}, [%4];"
                 : "=r"(r0), "=r"(r1), "=r"(r2), "=r"(r3) : "r"(addr));
}
__device__ __forceinline__ void mma_f16(float* c, uint32_t a0, uint32_t a1,
                                        uint32_t a2, uint32_t a3,
                                        uint32_t b0, uint32_t b1) {
    asm volatile("mma.sync.aligned.m16n8k16.row.col.f32.f16.f16.f32 "
                 "{%0,%1,%2,%3}, {%4,%5,%6,%7}, {%8,%9}, {%0,%1,%2,%3};"
                 : "+f"(c[0]), "+f"(c[1]), "+f"(c[2]), "+f"(c[3])
                 : "r"(a0), "r"(a1), "r"(a2), "r"(a3), "r"(b0), "r"(b1));
}
__device__ __forceinline__ void stg_cs_f2(float* p, float x, float y) {
    asm volatile("st.global.cs.v2.f32 [%0], {%1,%2};" :: "l"(p), "f"(x), "f"(y));
}

__device__ __forceinline__ void load_A_stage(uint32_t sA, const __half* Ah,
                                             int bm, int tid) {
    const int row = tid >> 1;
    const int cb = (tid & 1) * 4;
    const char* src = reinterpret_cast<const char*>(Ah + (size_t)(bm + row) * Hdim);
#pragma unroll
    for (int i = 0; i < 4; i++) {
        uint32_t off = SWZ128((uint32_t)(row * 128 + (cb + i) * 16));
        cp16(sA + off, src + (cb + i) * 16);
    }
}

__global__ void __launch_bounds__(256, 2)
logits_gemm(const __half* __restrict__ Ah, const __half* __restrict__ Bh,
            const float* __restrict__ bias, float* __restrict__ C)
{
    extern __shared__ char smem_raw[];
    const uint32_t sb0 = smem_u32(smem_raw);
    const uint32_t sb = (sb0 + 1023) & ~1023u;

    const int tid = threadIdx.x;
    const int lane = tid & 31;
    const int wid = tid >> 5;
    const int wm = wid & 3;
    const int wn = wid >> 2;
    const int bn0 = blockIdx.x * 128;
    const bool has2 = (bn0 + 64 < Vocab);
    const int bm0 = blockIdx.y * (NM_TILES * 128);

    // ---- resident B tiles (64 rows x 128B each), cp.async ----
    {
        const int row = tid >> 2;            // 0..63
        const int cb = (tid & 3) * 2;        // chunks 0,2,4,6
        const char* s0 = reinterpret_cast<const char*>(Bh + (size_t)(bn0 + row) * Hdim);
#pragma unroll
        for (int i = 0; i < 2; i++) {
            uint32_t off = SWZ128((uint32_t)(row * 128 + (cb + i) * 16));
            cp16(sb + LS_B0 + off, s0 + (cb + i) * 16);
        }
        if (has2) {
            const char* s1 = reinterpret_cast<const char*>(Bh + (size_t)(bn0 + 64 + row) * Hdim);
#pragma unroll
            for (int i = 0; i < 2; i++) {
                uint32_t off = SWZ128((uint32_t)(row * 128 + (cb + i) * 16));
                cp16(sb + LS_B1 + off, s1 + (cb + i) * 16);
            }
        }
    }
    load_A_stage(sb + LS_A, Ah, bm0, tid);
    cp_commit();

    const int gid = lane >> 2;
    const int tig = lane & 3;
    float2 bv[2][4];
#pragma unroll
    for (int g2 = 0; g2 < 2; g2++)
#pragma unroll
        for (int nt = 0; nt < 4; nt++) {
            int gn = bn0 + g2 * 64 + wn * 32 + nt * 8 + 2 * tig;
            bv[g2][nt] = (g2 == 0 || has2)
                ? *reinterpret_cast<const float2*>(bias + gn) : make_float2(0.f, 0.f);
        }

    const int rsel = lane & 15;
    const int csel = lane >> 4;

    for (int it = 0; it < NM_TILES; it++) {
        const uint32_t sA = sb + LS_A + (it & 1) * LS_ASTG;
        if (it + 1 < NM_TILES) {
            load_A_stage(sb + LS_A + ((it + 1) & 1) * LS_ASTG, Ah,
                         bm0 + (it + 1) * 128, tid);
            cp_commit();
            cp_wait<1>();
        } else {
            cp_wait<0>();
        }
        __syncthreads();

        float acc[2][2][4][4];   // [g2][mt][nt][frag]
#pragma unroll
        for (int g2 = 0; g2 < 2; g2++)
#pragma unroll
            for (int i = 0; i < 2; i++)
#pragma unroll
                for (int j = 0; j < 4; j++)
#pragma unroll
                    for (int f = 0; f < 4; f++) acc[g2][i][j][f] = 0.0f;

#pragma unroll
        for (int ks = 0; ks < 4; ks++) {
            const int col16 = ks * 2 + csel;
            uint32_t a[2][4];
#pragma unroll
            for (int mt = 0; mt < 2; mt++) {
                int row = wm * 32 + mt * 16 + rsel;
                uint32_t addr = sA + SWZ128((uint32_t)(row * 128 + col16 * 16));
                ldsm_x4(a[mt][0], a[mt][1], a[mt][2], a[mt][3], addr);
            }
#pragma unroll
            for (int g2 = 0; g2 < 2; g2++) {
                if (g2 == 1 && !has2) break;
                const uint32_t bB = sb + (g2 == 0 ? LS_B0 : LS_B1);
                uint32_t b0[4], b1[4];
#pragma unroll
                for (int np = 0; np < 2; np++) {
                    int row = wn * 32 + np * 16 + rsel;
                    uint32_t addr = bB + SWZ128((uint32_t)(row * 128 + col16 * 16));
                    uint32_t r0, r1, r2, r3;
                    ldsm_x4(r0, r1, r2, r3, addr);
                    b0[np * 2 + 0] = r0; b0[np * 2 + 1] = r1;
                    b1[np * 2 + 0] = r2; b1[np * 2 + 1] = r3;
                }
#pragma unroll
                for (int mt = 0; mt < 2; mt++)
#pragma unroll
                    for (int nt = 0; nt < 4; nt++)
                        mma_f16(acc[g2][mt][nt], a[mt][0], a[mt][1], a[mt][2], a[mt][3],
                                b0[nt], b1[nt]);
            }
        }

        const int bm = bm0 + it * 128;
#pragma unroll
        for (int g2 = 0; g2 < 2; g2++) {
            if (g2 == 1 && !has2) break;
#pragma unroll
            for (int nt = 0; nt < 4; nt++) {
                const int gn = bn0 + g2 * 64 + wn * 32 + nt * 8 + 2 * tig;
#pragma unroll
                for (int mt = 0; mt < 2; mt++) {
                    const int gm0 = bm + wm * 32 + mt * 16 + gid;
                    float x0 = fmaf(acc[g2][mt][nt][0], 0.125f, bv[g2][nt].x);
                    float y0 = fmaf(acc[g2][mt][nt][1], 0.125f, bv[g2][nt].y);
                    float x1 = fmaf(acc[g2][mt][nt][2], 0.125f, bv[g2][nt].x);
                    float y1 = fmaf(acc[g2][mt][nt][3], 0.125f, bv[g2][nt].y);
                    stg_cs_f2(C + (size_t)gm0 * Vocab + gn, x0, y0);
                    stg_cs_f2(C + (size_t)(gm0 + 8) * Vocab + gn, x1, y1);
                }
            }
        }
        __syncthreads();
    }
}

// ------------------------------------ launch --------------------------------------
extern "C" void kernel_launch(void* const* d_in, const int* in_sizes, int n_in,
                              void* d_out, int out_size)
{
    (void)in_sizes; (void)n_in; (void)out_size;
    const float* x     = (const float*)d_in[0];
    const float* W_ih0 = (const float*)d_in[1];
    const float* W_hh0 = (const float*)d_in[2];
    const float* b_ih0 = (const float*)d_in[3];
    const float* b_hh0 = (const float*)d_in[4];
    const float* W_ih1 = (const float*)d_in[5];
    const float* W_hh1 = (const float*)d_in[6];
    const float* b_ih1 = (const float*)d_in[7];
    const float* b_hh1 = (const float*)d_in[8];
    const float* Wl    = (const float*)d_in[9];
    const float* bl    = (const float*)d_in[10];
    float* out = (float*)d_out;

    void* p;
    cudaGetSymbolAddress(&p, g_xproj); float* xproj = (float*)p;
    cudaGetSymbolAddress(&p, g_h1);    float* h1    = (float*)p;
    cudaGetSymbolAddress(&p, g_Ah);    __half* Ah   = (__half*)p;
    cudaGetSymbolAddress(&p, g_Bh);    __half* Bh   = (__half*)p;

    // Wl -> fp16 (independent of LSTM chain)
    cvt_bh<<<(Vocab * Hdim + 255) / 256, 256>>>(Wl, Bh, Vocab * Hdim);

    // Layer 0 input projection
    gemm_nt_bias<<<dim3(Gdim / 64, Mrows / 64), 256>>>(
        x, W_ih0, b_ih0, b_hh0, xproj, Mrows, Gdim, INSZ);
    // Layer 0 recurrence -> h1 (fp32)
    lstm_layer<<<Bsz, Gdim>>>(xproj, W_hh0, h1, nullptr);
    // Layer 1 input projection
    gemm_nt_bias<<<dim3(Gdim / 64, Mrows / 64), 256>>>(
        h1, W_ih1, b_ih1, b_hh1, xproj, Mrows, Gdim, Hdim);
    // Layer 1 recurrence -> fp16 A directly
    lstm_layer<<<Bsz, Gdim>>>(xproj, W_hh1, nullptr, Ah);

    // Logits via pipelined HMMA fp16, paired-bn CTAs: 8000 = 62*128 + 64 -> 63 CTAs/x
    cudaFuncSetAttribute(logits_gemm, cudaFuncAttributeMaxDynamicSharedMemorySize, LG_SMEM);
    logits_gemm<<<dim3(63, Mrows / (NM_TILES * 128)), 256, LG_SMEM>>>(
        Ah, Bh, bl, out);
}

// round 14
// speedup vs baseline: 1.0316x; 1.0316x over previous
#include <cuda_runtime.h>
#include <cuda_fp16.h>
#include <cstdint>

// Problem constants
#define Bsz   64
#define Tlen  256
#define INSZ  256
#define Hdim  64
#define Gdim  256        // 4*Hdim
#define Vocab 8000
#define Mrows (Bsz * Tlen)   // 16384

// Scratch (device globals; no allocation allowed in kernel_launch)
__device__ float g_xproj[Mrows * Gdim];
__device__ float g_h1[Mrows * Hdim];
__device__ __align__(128) __half g_Ah[Mrows * Hdim];    // h2 rounded to fp16
__device__ __align__(128) __half g_Bh[Vocab * Hdim];    // 8*Wl rounded to fp16

// ---------------- packed f32x2 helpers ----------------
__device__ __forceinline__ unsigned long long pack2(float x) {
    unsigned long long r;
    asm("mov.b64 %0, {%1, %1};" : "=l"(r) : "f"(x));
    return r;
}
__device__ __forceinline__ unsigned long long pack2v(float x, float y) {
    unsigned long long r;
    asm("mov.b64 %0, {%1, %2};" : "=l"(r) : "f"(x), "f"(y));
    return r;
}
__device__ __forceinline__ void fma2(unsigned long long& d, unsigned long long a,
                                     unsigned long long b) {
    asm("fma.rn.f32x2 %0, %1, %2, %0;" : "+l"(d) : "l"(a), "l"(b));
}
__device__ __forceinline__ float2 unpack2(unsigned long long v) {
    float2 f;
    asm("mov.b64 {%0, %1}, %2;" : "=f"(f.x), "=f"(f.y) : "l"(v));
    return f;
}
__device__ __forceinline__ float fast_rcp(float x) {
    float r;
    asm("rcp.approx.f32 %0, %1;" : "=f"(r) : "f"(x));
    return r;
}
__device__ __forceinline__ float sigmoidf_(float x) {
    return fast_rcp(1.0f + __expf(-x));
}
__device__ __forceinline__ float tanh_fast(float x) {
    return 1.0f - 2.0f * fast_rcp(1.0f + __expf(2.0f * x));
}

// Dual 64-long dot sharing one set of h loads (16 LDS.128 feed both weight rows).
__device__ __forceinline__ float2 dot64v2(const unsigned long long* wa,
                                          const unsigned long long* wb,
                                          const float* h) {
    const ulonglong2* hp = reinterpret_cast<const ulonglong2*>(h);
    unsigned long long a0 = 0ULL, a1 = 0ULL, a2 = 0ULL, a3 = 0ULL;
    unsigned long long b0 = 0ULL, b1 = 0ULL, b2 = 0ULL, b3 = 0ULL;
#pragma unroll
    for (int j = 0; j < 16; j += 2) {
        ulonglong2 h01 = hp[j];
        ulonglong2 h23 = hp[j + 1];
        fma2(a0, wa[2 * j + 0], h01.x);  fma2(b0, wb[2 * j + 0], h01.x);
        fma2(a1, wa[2 * j + 1], h01.y);  fma2(b1, wb[2 * j + 1], h01.y);
        fma2(a2, wa[2 * j + 2], h23.x);  fma2(b2, wb[2 * j + 2], h23.x);
        fma2(a3, wa[2 * j + 3], h23.y);  fma2(b3, wb[2 * j + 3], h23.y);
    }
    float2 s0 = unpack2(a0), s1 = unpack2(a1), s2 = unpack2(a2), s3 = unpack2(a3);
    float2 t0 = unpack2(b0), t1 = unpack2(b1), t2 = unpack2(b2), t3 = unpack2(b3);
    float2 r;
    r.x = (((s0.x + s0.y) + (s1.x + s1.y)) + ((s2.x + s2.y) + (s3.x + s3.y)));
    r.y = (((t0.x + t0.y) + (t1.x + t1.y)) + ((t2.x + t2.y) + (t3.x + t3.y)));
    return r;
}

// ---------------- generic C[M,N] = A[M,K] * B[N,K]^T + bias1 (+bias2) ----------------
__global__ void gemm_nt_bias(const float* __restrict__ A, const float* __restrict__ Bm,
                             const float* __restrict__ bias1, const float* __restrict__ bias2,
                             float* __restrict__ C, int M, int N, int K)
{
    __shared__ __align__(16) float As[64][17];
    __shared__ __align__(16) float Bs[16][68];

    const int t  = threadIdx.x;
    const int bm = blockIdx.y * 64;
    const int bn = blockIdx.x * 64;
    const int tm = (t >> 4) << 2;
    const int tn = (t & 15) << 2;
    const int lr = t >> 2;
    const int lk = (t & 3) << 2;

    unsigned long long acc[4][2];
#pragma unroll
    for (int i = 0; i < 4; i++) { acc[i][0] = 0ULL; acc[i][1] = 0ULL; }

    const float* Aptr = A  + (size_t)(bm + lr) * K + lk;
    const float* Bptr = Bm + (size_t)(bn + lr) * K + lk;

    for (int k0 = 0; k0 < K; k0 += 16) {
        float4 av = *reinterpret_cast<const float4*>(Aptr + k0);
        float4 bv = *reinterpret_cast<const float4*>(Bptr + k0);
        As[lr][lk + 0] = av.x; As[lr][lk + 1] = av.y;
        As[lr][lk + 2] = av.z; As[lr][lk + 3] = av.w;
        Bs[lk + 0][lr] = bv.x; Bs[lk + 1][lr] = bv.y;
        Bs[lk + 2][lr] = bv.z; Bs[lk + 3][lr] = bv.w;
        __syncthreads();
#pragma unroll
        for (int kk = 0; kk < 16; kk++) {
            unsigned long long b0 =
                *reinterpret_cast<const unsigned long long*>(&Bs[kk][tn]);
            unsigned long long b1 =
                *reinterpret_cast<const unsigned long long*>(&Bs[kk][tn + 2]);
#pragma unroll
            for (int i = 0; i < 4; i++) {
                unsigned long long ap = pack2(As[tm + i][kk]);
                fma2(acc[i][0], ap, b0);
                fma2(acc[i][1], ap, b1);
            }
        }
        __syncthreads();
    }

    float4 bvec;
    bvec.x = bias1[bn + tn + 0];
    bvec.y = bias1[bn + tn + 1];
    bvec.z = bias1[bn + tn + 2];
    bvec.w = bias1[bn + tn + 3];
    if (bias2) {
        bvec.x += bias2[bn + tn + 0];
        bvec.y += bias2[bn + tn + 1];
        bvec.z += bias2[bn + tn + 2];
        bvec.w += bias2[bn + tn + 3];
    }
#pragma unroll
    for (int i = 0; i < 4; i++) {
        float2 lo = unpack2(acc[i][0]);
        float2 hi = unpack2(acc[i][1]);
        float4 v = make_float4(lo.x + bvec.x, lo.y + bvec.y,
                               hi.x + bvec.z, hi.y + bvec.w);
        *reinterpret_cast<float4*>(&C[(size_t)(bm + tm + i) * N + bn + tn]) = v;
    }
}

// ============ LSTM recurrence: 128 threads, 2 gates/thread, 1 shuffle, 1 barrier ====
// Thread (q,p): q = tid/2, p = tid&1.
//   p=0: gates i(q) [row q] and g(q) [row 128+q] -> computes i*g locally.
//   p=1: gates f(q) [row 64+q] and o(q) [row 192+q] -> receives i*g via shfl_xor(1),
//        runs the c/h tail and stores h.
__global__ void __launch_bounds__(128, 1)
lstm_layer(const float* __restrict__ xproj,   // [B,T,256] incl. biases
           const float* __restrict__ Whh,     // [256,64]
           float* __restrict__ hout,          // [B,T,64] fp32 or null
           __half* __restrict__ ah_out)       // [B,T,64] fp16 or null
{
    __shared__ __align__(16) float h_sh[2][Hdim];

    const int b = blockIdx.x;
    const int tid = threadIdx.x;
    const int q = tid >> 1;          // h index 0..63
    const int p = tid & 1;           // 0: (i,g)  1: (f,o)
    const int gA = p * Hdim + q;         // i or f
    const int gB = (p + 2) * Hdim + q;   // g or o

    unsigned long long wa[Hdim / 2], wb[Hdim / 2];
#pragma unroll
    for (int j = 0; j < Hdim / 2; j++) {
        float2 va = *reinterpret_cast<const float2*>(Whh + gA * Hdim + 2 * j);
        float2 vb = *reinterpret_cast<const float2*>(Whh + gB * Hdim + 2 * j);
        wa[j] = pack2v(va.x, va.y);
        wb[j] = pack2v(vb.x, vb.y);
    }

    if (tid < Hdim) { h_sh[0][tid] = 0.0f; h_sh[1][tid] = 0.0f; }
    __syncthreads();

    const float* xp = xproj + (size_t)b * Tlen * Gdim;
    float xA = xp[gA];
    float xB = xp[gB];
    float c = 0.0f;

    for (int t = 0; t < Tlen; t++) {
        float2 d = dot64v2(wa, wb, h_sh[t & 1]);
        float vA = xA + d.x;
        float vB = xB + d.y;
        if (t + 1 < Tlen) {
            xA = xp[(size_t)(t + 1) * Gdim + gA];
            xB = xp[(size_t)(t + 1) * Gdim + gB];
        }

        // p=0: actA=i, actB=g(tanh);  p=1: actA=f, actB=o (both sigmoid)
        float actA = sigmoidf_(vA);
        float actB = (p == 0) ? tanh_fast(vB) : sigmoidf_(vB);
        float send = actA * actB;            // p=0: i*g (p=1's value unused)
        float ig = __shfl_xor_sync(0xffffffffu, send, 1);

        if (p == 1) {
            c = actA * c + ig;               // c = f*c + i*g
            float hn = actB * tanh_fast(c);  // h = o*tanh(c)
            h_sh[(t + 1) & 1][q] = hn;
            size_t idx = ((size_t)b * Tlen + t) * Hdim + q;
            if (hout) hout[idx] = hn;
            if (ah_out) ah_out[idx] = __float2half(hn);
        }
        __syncthreads();
    }
}

// ---------------- Wl -> fp16 (scaled by 8 for fp16 normal range) -------
__global__ void cvt_bh(const float* __restrict__ in, __half* __restrict__ out, int n)
{
    int i = blockIdx.x * blockDim.x + threadIdx.x;
    if (i < n) out[i] = __float2half(in[i] * 8.0f);
}

// ============ HMMA fp16 logits GEMM (byte-identical to passing R7) ==================
#define SWZ128(off) ((off) ^ (((off) >> 3) & 0x70))
#define LS_B    0
#define LS_A    8192
#define LS_ASTG 16384
#define LG_SMEM (8192 + 2 * 16384 + 1024)
#define NM_TILES 8

static __device__ __forceinline__ uint32_t smem_u32(const void* p) {
    uint32_t a;
    asm("{ .reg .u64 t; cvta.to.shared.u64 t, %1; cvt.u32.u64 %0, t; }"
        : "=r"(a) : "l"(p));
    return a;
}
__device__ __forceinline__ void cp16(uint32_t dst, const void* src) {
    asm volatile("cp.async.cg.shared.global [%0], [%1], 16;"
                 :: "r"(dst), "l"(src));
}
__device__ __forceinline__ void cp_commit() {
    asm volatile("cp.async.commit_group;" ::: "memory");
}
template <int N>
__device__ __forceinline__ void cp_wait() {
    asm volatile("cp.async.wait_group %0;" :: "n"(N) : "memory");
}
__device__ __forceinline__ void ldsm_x4(uint32_t& r0, uint32_t& r1, uint32_t& r2,
                                        uint32_t& r3, uint32_t addr) {
    asm volatile("ldmatrix.sync.aligned.m8n8.x4.shared.b16 {%0,%1,%2,%3}, [%4];"
                 : "=r"(r0), "=r"(r1), "=r"(r2), "=r"(r3) : "r"(addr));
}
__device__ __forceinline__ void mma_f16(float* c, uint32_t a0, uint32_t a1,
                                        uint32_t a2, uint32_t a3,
                                        uint32_t b0, uint32_t b1) {
    asm volatile("mma.sync.aligned.m16n8k16.row.col.f32.f16.f16.f32 "
                 "{%0,%1,%2,%3}, {%4,%5,%6,%7}, {%8,%9}, {%0,%1,%2,%3};"
                 : "+f"(c[0]), "+f"(c[1]), "+f"(c[2]), "+f"(c[3])
                 : "r"(a0), "r"(a1), "r"(a2), "r"(a3), "r"(b0), "r"(b1));
}
__device__ __forceinline__ void stg_cs_f2(float* p, float x, float y) {
    asm volatile("st.global.cs.v2.f32 [%0], {%1,%2};" :: "l"(p), "f"(x), "f"(y));
}

__device__ __forceinline__ void load_A_stage(uint32_t sA, const __half* Ah,
                                             int bm, int tid) {
    const int row = tid >> 1;
    const int cb = (tid & 1) * 4;
    const char* src = reinterpret_cast<const char*>(Ah + (size_t)(bm + row) * Hdim);
#pragma unroll
    for (int i = 0; i < 4; i++) {
        uint32_t off = SWZ128((uint32_t)(row * 128 + (cb + i) * 16));
        cp16(sA + off, src + (cb + i) * 16);
    }
}

__global__ void __launch_bounds__(256)
logits_gemm(const __half* __restrict__ Ah, const __half* __restrict__ Bh,
            const float* __restrict__ bias, float* __restrict__ C)
{
    extern __shared__ char smem_raw[];
    const uint32_t sb0 = smem_u32(smem_raw);
    const uint32_t sb = (sb0 + 1023) & ~1023u;

    const int tid = threadIdx.x;
    const int lane = tid & 31;
    const int wid = tid >> 5;
    const int wm = wid & 3;
    const int wn = wid >> 2;
    const int bn = blockIdx.x * 64;
    const int bm0 = blockIdx.y * (NM_TILES * 128);

    {
        const int row = tid >> 2;
        const int cb = (tid & 3) * 2;
        const char* src = reinterpret_cast<const char*>(Bh + (size_t)(bn + row) * Hdim);
#pragma unroll
        for (int i = 0; i < 2; i++) {
            uint32_t off = SWZ128((uint32_t)(row * 128 + (cb + i) * 16));
            cp16(sb + LS_B + off, src + (cb + i) * 16);
        }
    }
    load_A_stage(sb + LS_A, Ah, bm0, tid);
    cp_commit();

    const int gid = lane >> 2;
    const int tig = lane & 3;
    float2 bv[4];
#pragma unroll
    for (int nt = 0; nt < 4; nt++)
        bv[nt] = *reinterpret_cast<const float2*>(bias + bn + wn * 32 + nt * 8 + 2 * tig);

    const int rsel = lane & 15;
    const int csel = lane >> 4;

    for (int it = 0; it < NM_TILES; it++) {
        const uint32_t sA = sb + LS_A + (it & 1) * LS_ASTG;
        if (it + 1 < NM_TILES) {
            load_A_stage(sb + LS_A + ((it + 1) & 1) * LS_ASTG, Ah,
                         bm0 + (it + 1) * 128, tid);
            cp_commit();
            cp_wait<1>();
        } else {
            cp_wait<0>();
        }
        __syncthreads();

        float acc[2][4][4];
#pragma unroll
        for (int i = 0; i < 2; i++)
#pragma unroll
            for (int j = 0; j < 4; j++)
#pragma unroll
                for (int q = 0; q < 4; q++) acc[i][j][q] = 0.0f;

#pragma unroll
        for (int ks = 0; ks < 4; ks++) {
            const int col16 = ks * 2 + csel;
            uint32_t a[2][4];
#pragma unroll
            for (int mt = 0; mt < 2; mt++) {
                int row = wm * 32 + mt * 16 + rsel;
                uint32_t addr = sA + SWZ128((uint32_t)(row * 128 + col16 * 16));
                ldsm_x4(a[mt][0], a[mt][1], a[mt][2], a[mt][3], addr);
            }
            uint32_t b0[4], b1[4];
#pragma unroll
            for (int np = 0; np < 2; np++) {
                int row = wn * 32 + np * 16 + rsel;
                uint32_t addr = sb + LS_B + SWZ128((uint32_t)(row * 128 + col16 * 16));
                uint32_t r0, r1, r2, r3;
                ldsm_x4(r0, r1, r2, r3, addr);
                b0[np * 2 + 0] = r0; b0[np * 2 + 1] = r1;
                b1[np * 2 + 0] = r2; b1[np * 2 + 1] = r3;
            }
#pragma unroll
            for (int mt = 0; mt < 2; mt++)
#pragma unroll
                for (int nt = 0; nt < 4; nt++)
                    mma_f16(acc[mt][nt], a[mt][0], a[mt][1], a[mt][2], a[mt][3],
                            b0[nt], b1[nt]);
        }

        const int bm = bm0 + it * 128;
#pragma unroll
        for (int nt = 0; nt < 4; nt++) {
            const int gn = bn + wn * 32 + nt * 8 + 2 * tig;
#pragma unroll
            for (int mt = 0; mt < 2; mt++) {
                const int gm0 = bm + wm * 32 + mt * 16 + gid;
                float x0 = fmaf(acc[mt][nt][0], 0.125f, bv[nt].x);
                float y0 = fmaf(acc[mt][nt][1], 0.125f, bv[nt].y);
                float x1 = fmaf(acc[mt][nt][2], 0.125f, bv[nt].x);
                float y1 = fmaf(acc[mt][nt][3], 0.125f, bv[nt].y);
                stg_cs_f2(C + (size_t)gm0 * Vocab + gn, x0, y0);
                stg_cs_f2(C + (size_t)(gm0 + 8) * Vocab + gn, x1, y1);
            }
        }
        __syncthreads();
    }
}

// ------------------------------------ launch --------------------------------------
extern "C" void kernel_launch(void* const* d_in, const int* in_sizes, int n_in,
                              void* d_out, int out_size)
{
    (void)in_sizes; (void)n_in; (void)out_size;
    const float* x     = (const float*)d_in[0];
    const float* W_ih0 = (const float*)d_in[1];
    const float* W_hh0 = (const float*)d_in[2];
    const float* b_ih0 = (const float*)d_in[3];
    const float* b_hh0 = (const float*)d_in[4];
    const float* W_ih1 = (const float*)d_in[5];
    const float* W_hh1 = (const float*)d_in[6];
    const float* b_ih1 = (const float*)d_in[7];
    const float* b_hh1 = (const float*)d_in[8];
    const float* Wl    = (const float*)d_in[9];
    const float* bl    = (const float*)d_in[10];
    float* out = (float*)d_out;

    void* p;
    cudaGetSymbolAddress(&p, g_xproj); float* xproj = (float*)p;
    cudaGetSymbolAddress(&p, g_h1);    float* h1    = (float*)p;
    cudaGetSymbolAddress(&p, g_Ah);    __half* Ah   = (__half*)p;
    cudaGetSymbolAddress(&p, g_Bh);    __half* Bh   = (__half*)p;

    // Wl -> fp16 (independent of LSTM chain)
    cvt_bh<<<(Vocab * Hdim + 255) / 256, 256>>>(Wl, Bh, Vocab * Hdim);

    // Layer 0 input projection
    gemm_nt_bias<<<dim3(Gdim / 64, Mrows / 64), 256>>>(
        x, W_ih0, b_ih0, b_hh0, xproj, Mrows, Gdim, INSZ);
    // Layer 0 recurrence -> h1 (fp32)
    lstm_layer<<<Bsz, 128>>>(xproj, W_hh0, h1, nullptr);
    // Layer 1 input projection
    gemm_nt_bias<<<dim3(Gdim / 64, Mrows / 64), 256>>>(
        h1, W_ih1, b_ih1, b_hh1, xproj, Mrows, Gdim, Hdim);
    // Layer 1 recurrence -> fp16 A directly
    lstm_layer<<<Bsz, 128>>>(xproj, W_hh1, nullptr, Ah);

    // Logits via pipelined HMMA fp16 single pass
    cudaFuncSetAttribute(logits_gemm, cudaFuncAttributeMaxDynamicSharedMemorySize, LG_SMEM);
    logits_gemm<<<dim3(Vocab / 64, Mrows / (NM_TILES * 128)), 256, LG_SMEM>>>(
        Ah, Bh, bl, out);
}

// round 15
// speedup vs baseline: 1.0449x; 1.0129x over previous
#include <cuda_runtime.h>
#include <cuda_fp16.h>
#include <cstdint>

// Problem constants
#define Bsz   64
#define Tlen  256
#define INSZ  256
#define Hdim  64
#define Gdim  256        // 4*Hdim
#define Vocab 8000
#define Mrows (Bsz * Tlen)   // 16384

// Scratch (device globals; no allocation allowed in kernel_launch)
__device__ float g_xproj[Mrows * Gdim];
__device__ float g_h1[Mrows * Hdim];
__device__ __align__(128) __half g_Ah[Mrows * Hdim];    // h2 rounded to fp16
__device__ __align__(128) __half g_Bh[Vocab * Hdim];    // 8*Wl rounded to fp16

// ---------------- packed f32x2 helpers ----------------
__device__ __forceinline__ unsigned long long pack2(float x) {
    unsigned long long r;
    asm("mov.b64 %0, {%1, %1};" : "=l"(r) : "f"(x));
    return r;
}
__device__ __forceinline__ unsigned long long pack2v(float x, float y) {
    unsigned long long r;
    asm("mov.b64 %0, {%1, %2};" : "=l"(r) : "f"(x), "f"(y));
    return r;
}
__device__ __forceinline__ void fma2(unsigned long long& d, unsigned long long a,
                                     unsigned long long b) {
    asm("fma.rn.f32x2 %0, %1, %2, %0;" : "+l"(d) : "l"(a), "l"(b));
}
__device__ __forceinline__ float2 unpack2(unsigned long long v) {
    float2 f;
    asm("mov.b64 {%0, %1}, %2;" : "=f"(f.x), "=f"(f.y) : "l"(v));
    return f;
}
__device__ __forceinline__ float fast_rcp(float x) {
    float r;
    asm("rcp.approx.f32 %0, %1;" : "=f"(r) : "f"(x));
    return r;
}
__device__ __forceinline__ float sigmoidf_(float x) {
    return fast_rcp(1.0f + __expf(-x));
}
__device__ __forceinline__ float tanh_fast(float x) {
    return 1.0f - 2.0f * fast_rcp(1.0f + __expf(2.0f * x));
}
// 64-long dot via LDS.128: wp = 32 packed f32x2, h = 64 floats (16B-aligned SMEM).
__device__ __forceinline__ float dot64v(const unsigned long long* wp, const float* h) {
    const ulonglong2* hp = reinterpret_cast<const ulonglong2*>(h);
    unsigned long long a0 = 0ULL, a1 = 0ULL, a2 = 0ULL, a3 = 0ULL;
#pragma unroll
    for (int j = 0; j < 16; j += 2) {
        ulonglong2 h01 = hp[j];
        ulonglong2 h23 = hp[j + 1];
        fma2(a0, wp[2 * j + 0], h01.x);
        fma2(a1, wp[2 * j + 1], h01.y);
        fma2(a2, wp[2 * j + 2], h23.x);
        fma2(a3, wp[2 * j + 3], h23.y);
    }
    float2 s0 = unpack2(a0), s1 = unpack2(a1), s2 = unpack2(a2), s3 = unpack2(a3);
    return (((s0.x + s0.y) + (s1.x + s1.y)) + ((s2.x + s2.y) + (s3.x + s3.y)));
}

// ---------------- cp.async helpers ----------------
static __device__ __forceinline__ uint32_t smem_u32(const void* p) {
    uint32_t a;
    asm("{ .reg .u64 t; cvta.to.shared.u64 t, %1; cvt.u32.u64 %0, t; }"
        : "=r"(a) : "l"(p));
    return a;
}
__device__ __forceinline__ void cp16(uint32_t dst, const void* src) {
    asm volatile("cp.async.cg.shared.global [%0], [%1], 16;"
                 :: "r"(dst), "l"(src));
}
__device__ __forceinline__ void cp_commit() {
    asm volatile("cp.async.commit_group;" ::: "memory");
}
template <int N>
__device__ __forceinline__ void cp_wait() {
    asm volatile("cp.async.wait_group %0;" :: "n"(N) : "memory");
}

// ---------------- generic C[M,N] = A[M,K] * B[N,K]^T + bias1 (+bias2) ----------------
__global__ void gemm_nt_bias(const float* __restrict__ A, const float* __restrict__ Bm,
                             const float* __restrict__ bias1, const float* __restrict__ bias2,
                             float* __restrict__ C, int M, int N, int K)
{
    __shared__ __align__(16) float As[64][17];
    __shared__ __align__(16) float Bs[16][68];

    const int t  = threadIdx.x;
    const int bm = blockIdx.y * 64;
    const int bn = blockIdx.x * 64;
    const int tm = (t >> 4) << 2;
    const int tn = (t & 15) << 2;
    const int lr = t >> 2;
    const int lk = (t & 3) << 2;

    unsigned long long acc[4][2];
#pragma unroll
    for (int i = 0; i < 4; i++) { acc[i][0] = 0ULL; acc[i][1] = 0ULL; }

    const float* Aptr = A  + (size_t)(bm + lr) * K + lk;
    const float* Bptr = Bm + (size_t)(bn + lr) * K + lk;

    for (int k0 = 0; k0 < K; k0 += 16) {
        float4 av = *reinterpret_cast<const float4*>(Aptr + k0);
        float4 bv = *reinterpret_cast<const float4*>(Bptr + k0);
        As[lr][lk + 0] = av.x; As[lr][lk + 1] = av.y;
        As[lr][lk + 2] = av.z; As[lr][lk + 3] = av.w;
        Bs[lk + 0][lr] = bv.x; Bs[lk + 1][lr] = bv.y;
        Bs[lk + 2][lr] = bv.z; Bs[lk + 3][lr] = bv.w;
        __syncthreads();
#pragma unroll
        for (int kk = 0; kk < 16; kk++) {
            unsigned long long b0 =
                *reinterpret_cast<const unsigned long long*>(&Bs[kk][tn]);
            unsigned long long b1 =
                *reinterpret_cast<const unsigned long long*>(&Bs[kk][tn + 2]);
#pragma unroll
            for (int i = 0; i < 4; i++) {
                unsigned long long ap = pack2(As[tm + i][kk]);
                fma2(acc[i][0], ap, b0);
                fma2(acc[i][1], ap, b1);
            }
        }
        __syncthreads();
    }

    float4 bvec;
    bvec.x = bias1[bn + tn + 0];
    bvec.y = bias1[bn + tn + 1];
    bvec.z = bias1[bn + tn + 2];
    bvec.w = bias1[bn + tn + 3];
    if (bias2) {
        bvec.x += bias2[bn + tn + 0];
        bvec.y += bias2[bn + tn + 1];
        bvec.z += bias2[bn + tn + 2];
        bvec.w += bias2[bn + tn + 3];
    }
#pragma unroll
    for (int i = 0; i < 4; i++) {
        float2 lo = unpack2(acc[i][0]);
        float2 hi = unpack2(acc[i][1]);
        float4 v = make_float4(lo.x + bvec.x, lo.y + bvec.y,
                               hi.x + bvec.z, hi.y + bvec.w);
        *reinterpret_cast<float4*>(&C[(size_t)(bm + tm + i) * N + bn + tn]) = v;
    }
}

// ============ LSTM recurrence: quad-shuffle + SMEM-staged xproj (cp.async) ==========
// xproj consumed from SMEM chunks of 8 steps (8KB), double-buffered, prefetched a
// full chunk ahead — no per-step LDG anywhere near the critical path.
#define XCH 8                     // steps per chunk
#define NCH (Tlen / XCH)          // 32 chunks

__global__ void __launch_bounds__(256, 1)
lstm_layer(const float* __restrict__ xproj,   // [B,T,256] incl. biases
           const float* __restrict__ Whh,     // [256,64]
           float* __restrict__ hout,          // [B,T,64] fp32 or null
           __half* __restrict__ ah_out)       // [B,T,64] fp16 or null
{
    __shared__ __align__(16) float h_sh[2][Hdim];
    __shared__ __align__(16) float xs[2][XCH * Gdim];   // 2 x 8KB

    const int b = blockIdx.x;
    const int tid = threadIdx.x;
    const int q = tid >> 2;          // h index 0..63
    const int k = tid & 3;           // gate type 0=i 1=f 2=g 3=o
    const int base = (tid & 31) & ~3;
    const int gidx = k * Hdim + q;   // weight row / xproj column

    unsigned long long wp[Hdim / 2];
#pragma unroll
    for (int j = 0; j < Hdim / 2; j++) {
        float2 v = *reinterpret_cast<const float2*>(Whh + gidx * Hdim + 2 * j);
        wp[j] = pack2v(v.x, v.y);
    }

    if (tid < Hdim) { h_sh[0][tid] = 0.0f; h_sh[1][tid] = 0.0f; }

    const float* xp = xproj + (size_t)b * Tlen * Gdim;
    // each thread copies 8 floats (2 x 16B) per chunk
    const uint32_t xs0 = smem_u32(&xs[0][0]);
    const uint32_t xs1 = smem_u32(&xs[1][0]);
    {
        const float* s0 = xp + tid * 8;                  // chunk 0
        cp16(xs0 + tid * 32, s0);
        cp16(xs0 + tid * 32 + 16, s0 + 4);
        cp_commit();
        const float* s1 = xp + XCH * Gdim + tid * 8;     // chunk 1
        cp16(xs1 + tid * 32, s1);
        cp16(xs1 + tid * 32 + 16, s1 + 4);
        cp_commit();
    }

    float c = 0.0f;

    for (int t = 0; t < Tlen; t++) {
        if ((t & (XCH - 1)) == 0) {
            const int kch = t >> 3;
            if (kch >= 1 && kch + 1 < NCH) {
                // refill the buffer just freed (held chunk kch-1)
                const uint32_t dst = ((kch + 1) & 1) ? xs1 : xs0;
                const float* src = xp + (size_t)(kch + 1) * XCH * Gdim + tid * 8;
                cp16(dst + tid * 32, src);
                cp16(dst + tid * 32 + 16, src + 4);
                cp_commit();
                cp_wait<1>();      // chunk kch complete
            } else {
                cp_wait<0>();      // startup / tail: everything complete
            }
            __syncthreads();       // chunk visible to all (also covers h_sh init)
        }

        const float xcur = xs[(t >> 3) & 1][(t & (XCH - 1)) * Gdim + gidx];
        float val = xcur + dot64v(wp, h_sh[t & 1]);

        float act = (k == 2) ? tanh_fast(val) : sigmoidf_(val);

        float iv = __shfl_sync(0xffffffffu, act, base + 0);
        float fv = __shfl_sync(0xffffffffu, act, base + 1);
        float gv = __shfl_sync(0xffffffffu, act, base + 2);
        float ov = __shfl_sync(0xffffffffu, act, base + 3);

        c = fv * c + iv * gv;
        float hn = ov * tanh_fast(c);

        if (k == 0) {
            h_sh[(t + 1) & 1][q] = hn;
            size_t idx = ((size_t)b * Tlen + t) * Hdim + q;
            if (hout) hout[idx] = hn;
            if (ah_out) ah_out[idx] = __float2half(hn);
        }
        __syncthreads();
    }
}

// ---------------- Wl -> fp16 (scaled by 8 for fp16 normal range) -------
__global__ void cvt_bh(const float* __restrict__ in, __half* __restrict__ out, int n)
{
    int i = blockIdx.x * blockDim.x + threadIdx.x;
    if (i < n) out[i] = __float2half(in[i] * 8.0f);
}

// ============ HMMA fp16 logits GEMM: sequential bn-pair (A SMEM reuse) ==============
// CTA owns two 64-col bn halves (B0/B1 resident, 16KB) and processes them
// SEQUENTIALLY per A stage — same register footprint as the proven single-bn kernel,
// but each A tile is read from L2 once per 128 output columns instead of per 64.
#define SWZ128(off) ((off) ^ (((off) >> 3) & 0x70))
#define LS_B0   0
#define LS_B1   8192
#define LS_A    16384
#define LS_ASTG 16384
#define LG_SMEM (16384 + 2 * 16384 + 1024)
#define NM_TILES 8

__device__ __forceinline__ void ldsm_x4(uint32_t& r0, uint32_t& r1, uint32_t& r2,
                                        uint32_t& r3, uint32_t addr) {
    asm volatile("ldmatrix.sync.aligned.m8n8.x4.shared.b16 {%0,%1,%2,%3}, [%4];"
                 : "=r"(r0), "=r"(r1), "=r"(r2), "=r"(r3) : "r"(addr));
}
__device__ __forceinline__ void mma_f16(float* c, uint32_t a0, uint32_t a1,
                                        uint32_t a2, uint32_t a3,
                                        uint32_t b0, uint32_t b1) {
    asm volatile("mma.sync.aligned.m16n8k16.row.col.f32.f16.f16.f32 "
                 "{%0,%1,%2,%3}, {%4,%5,%6,%7}, {%8,%9}, {%0,%1,%2,%3};"
                 : "+f"(c[0]), "+f"(c[1]), "+f"(c[2]), "+f"(c[3])
                 : "r"(a0), "r"(a1), "r"(a2), "r"(a3), "r"(b0), "r"(b1));
}
__device__ __forceinline__ void stg_cs_f2(float* p, float x, float y) {
    asm volatile("st.global.cs.v2.f32 [%0], {%1,%2};" :: "l"(p), "f"(x), "f"(y));
}

__device__ __forceinline__ void load_A_stage(uint32_t sA, const __half* Ah,
                                             int bm, int tid) {
    const int row = tid >> 1;
    const int cb = (tid & 1) * 4;
    const char* src = reinterpret_cast<const char*>(Ah + (size_t)(bm + row) * Hdim);
#pragma unroll
    for (int i = 0; i < 4; i++) {
        uint32_t off = SWZ128((uint32_t)(row * 128 + (cb + i) * 16));
        cp16(sA + off, src + (cb + i) * 16);
    }
}

__global__ void __launch_bounds__(256)
logits_gemm(const __half* __restrict__ Ah, const __half* __restrict__ Bh,
            const float* __restrict__ bias, float* __restrict__ C)
{
    extern __shared__ char smem_raw[];
    const uint32_t sb0 = smem_u32(smem_raw);
    const uint32_t sb = (sb0 + 1023) & ~1023u;

    const int tid = threadIdx.x;
    const int lane = tid & 31;
    const int wid = tid >> 5;
    const int wm = wid & 3;
    const int wn = wid >> 2;
    const int bn0 = blockIdx.x * 128;
    const bool has2 = (bn0 + 64 < Vocab);
    const int bm0 = blockIdx.y * (NM_TILES * 128);

    // resident B tiles
    {
        const int row = tid >> 2;
        const int cb = (tid & 3) * 2;
        const char* s0 = reinterpret_cast<const char*>(Bh + (size_t)(bn0 + row) * Hdim);
#pragma unroll
        for (int i = 0; i < 2; i++) {
            uint32_t off = SWZ128((uint32_t)(row * 128 + (cb + i) * 16));
            cp16(sb + LS_B0 + off, s0 + (cb + i) * 16);
        }
        if (has2) {
            const char* s1 = reinterpret_cast<const char*>(Bh + (size_t)(bn0 + 64 + row) * Hdim);
#pragma unroll
            for (int i = 0; i < 2; i++) {
                uint32_t off = SWZ128((uint32_t)(row * 128 + (cb + i) * 16));
                cp16(sb + LS_B1 + off, s1 + (cb + i) * 16);
            }
        }
    }
    load_A_stage(sb + LS_A, Ah, bm0, tid);
    cp_commit();

    const int gid = lane >> 2;
    const int tig = lane & 3;
    const int rsel = lane & 15;
    const int csel = lane >> 4;

    for (int it = 0; it < NM_TILES; it++) {
        const uint32_t sA = sb + LS_A + (it & 1) * LS_ASTG;
        if (it + 1 < NM_TILES) {
            load_A_stage(sb + LS_A + ((it + 1) & 1) * LS_ASTG, Ah,
                         bm0 + (it + 1) * 128, tid);
            cp_commit();
            cp_wait<1>();
        } else {
            cp_wait<0>();
        }
        __syncthreads();

        const int bm = bm0 + it * 128;

#pragma unroll
        for (int g2 = 0; g2 < 2; g2++) {
            if (g2 == 1 && !has2) break;
            const uint32_t bB = sb + (g2 == 0 ? LS_B0 : LS_B1);
            const int bn = bn0 + g2 * 64;

            float acc[2][4][4];
#pragma unroll
            for (int i = 0; i < 2; i++)
#pragma unroll
                for (int j = 0; j < 4; j++)
#pragma unroll
                    for (int f = 0; f < 4; f++) acc[i][j][f] = 0.0f;

#pragma unroll
            for (int ks = 0; ks < 4; ks++) {
                const int col16 = ks * 2 + csel;
                uint32_t a[2][4];
#pragma unroll
                for (int mt = 0; mt < 2; mt++) {
                    int row = wm * 32 + mt * 16 + rsel;
                    uint32_t addr = sA + SWZ128((uint32_t)(row * 128 + col16 * 16));
                    ldsm_x4(a[mt][0], a[mt][1], a[mt][2], a[mt][3], addr);
                }
                uint32_t b0[4], b1[4];
#pragma unroll
                for (int np = 0; np < 2; np++) {
                    int row = wn * 32 + np * 16 + rsel;
                    uint32_t addr = bB + SWZ128((uint32_t)(row * 128 + col16 * 16));
                    uint32_t r0, r1, r2, r3;
                    ldsm_x4(r0, r1, r2, r3, addr);
                    b0[np * 2 + 0] = r0; b0[np * 2 + 1] = r1;
                    b1[np * 2 + 0] = r2; b1[np * 2 + 1] = r3;
                }
#pragma unroll
                for (int mt = 0; mt < 2; mt++)
#pragma unroll
                    for (int nt = 0; nt < 4; nt++)
                        mma_f16(acc[mt][nt], a[mt][0], a[mt][1], a[mt][2], a[mt][3],
                                b0[nt], b1[nt]);
            }

#pragma unroll
            for (int nt = 0; nt < 4; nt++) {
                const int gn = bn + wn * 32 + nt * 8 + 2 * tig;
                float2 bv = *reinterpret_cast<const float2*>(bias + gn);
#pragma unroll
                for (int mt = 0; mt < 2; mt++) {
                    const int gm0 = bm + wm * 32 + mt * 16 + gid;
                    float x0 = fmaf(acc[mt][nt][0], 0.125f, bv.x);
                    float y0 = fmaf(acc[mt][nt][1], 0.125f, bv.y);
                    float x1 = fmaf(acc[mt][nt][2], 0.125f, bv.x);
                    float y1 = fmaf(acc[mt][nt][3], 0.125f, bv.y);
                    stg_cs_f2(C + (size_t)gm0 * Vocab + gn, x0, y0);
                    stg_cs_f2(C + (size_t)(gm0 + 8) * Vocab + gn, x1, y1);
                }
            }
        }
        __syncthreads();
    }
}

// ------------------------------------ launch --------------------------------------
extern "C" void kernel_launch(void* const* d_in, const int* in_sizes, int n_in,
                              void* d_out, int out_size)
{
    (void)in_sizes; (void)n_in; (void)out_size;
    const float* x     = (const float*)d_in[0];
    const float* W_ih0 = (const float*)d_in[1];
    const float* W_hh0 = (const float*)d_in[2];
    const float* b_ih0 = (const float*)d_in[3];
    const float* b_hh0 = (const float*)d_in[4];
    const float* W_ih1 = (const float*)d_in[5];
    const float* W_hh1 = (const float*)d_in[6];
    const float* b_ih1 = (const float*)d_in[7];
    const float* b_hh1 = (const float*)d_in[8];
    const float* Wl    = (const float*)d_in[9];
    const float* bl    = (const float*)d_in[10];
    float* out = (float*)d_out;

    void* p;
    cudaGetSymbolAddress(&p, g_xproj); float* xproj = (float*)p;
    cudaGetSymbolAddress(&p, g_h1);    float* h1    = (float*)p;
    cudaGetSymbolAddress(&p, g_Ah);    __half* Ah   = (__half*)p;
    cudaGetSymbolAddress(&p, g_Bh);    __half* Bh   = (__half*)p;

    // Wl -> fp16 (independent of LSTM chain)
    cvt_bh<<<(Vocab * Hdim + 255) / 256, 256>>>(Wl, Bh, Vocab * Hdim);

    // Layer 0 input projection
    gemm_nt_bias<<<dim3(Gdim / 64, Mrows / 64), 256>>>(
        x, W_ih0, b_ih0, b_hh0, xproj, Mrows, Gdim, INSZ);
    // Layer 0 recurrence -> h1 (fp32)
    lstm_layer<<<Bsz, Gdim>>>(xproj, W_hh0, h1, nullptr);
    // Layer 1 input projection
    gemm_nt_bias<<<dim3(Gdim / 64, Mrows / 64), 256>>>(
        h1, W_ih1, b_ih1, b_hh1, xproj, Mrows, Gdim, Hdim);
    // Layer 1 recurrence -> fp16 A directly
    lstm_layer<<<Bsz, Gdim>>>(xproj, W_hh1, nullptr, Ah);

    // Logits: sequential bn-pair CTAs, 8000 = 62*128 + 64 -> 63 CTAs in x
    cudaFuncSetAttribute(logits_gemm, cudaFuncAttributeMaxDynamicSharedMemorySize, LG_SMEM);
    logits_gemm<<<dim3(63, Mrows / (NM_TILES * 128)), 256, LG_SMEM>>>(
        Ah, Bh, bl, out);
}

// round 16
// speedup vs baseline: 1.0462x; 1.0012x over previous
#include <cuda_runtime.h>
#include <cuda_fp16.h>
#include <cstdint>

// Problem constants
#define Bsz   64
#define Tlen  256
#define INSZ  256
#define Hdim  64
#define Gdim  256        // 4*Hdim
#define Vocab 8000
#define Mrows (Bsz * Tlen)   // 16384

// Scratch (device globals; no allocation allowed in kernel_launch)
__device__ float g_xproj[Mrows * Gdim];
__device__ float g_h1[Mrows * Hdim];
__device__ __align__(128) __half g_Ah[Mrows * Hdim];    // h2 rounded to fp16
__device__ __align__(128) __half g_Bh[Vocab * Hdim];    // 8*Wl rounded to fp16

// ---------------- packed f32x2 helpers ----------------
__device__ __forceinline__ unsigned long long pack2(float x) {
    unsigned long long r;
    asm("mov.b64 %0, {%1, %1};" : "=l"(r) : "f"(x));
    return r;
}
__device__ __forceinline__ unsigned long long pack2v(float x, float y) {
    unsigned long long r;
    asm("mov.b64 %0, {%1, %2};" : "=l"(r) : "f"(x), "f"(y));
    return r;
}
__device__ __forceinline__ void fma2(unsigned long long& d, unsigned long long a,
                                     unsigned long long b) {
    asm("fma.rn.f32x2 %0, %1, %2, %0;" : "+l"(d) : "l"(a), "l"(b));
}
__device__ __forceinline__ float2 unpack2(unsigned long long v) {
    float2 f;
    asm("mov.b64 {%0, %1}, %2;" : "=f"(f.x), "=f"(f.y) : "l"(v));
    return f;
}
__device__ __forceinline__ float fast_rcp(float x) {
    float r;
    asm("rcp.approx.f32 %0, %1;" : "=f"(r) : "f"(x));
    return r;
}
__device__ __forceinline__ float sigmoidf_(float x) {
    return fast_rcp(1.0f + __expf(-x));
}
__device__ __forceinline__ float tanh_fast(float x) {
    return 1.0f - 2.0f * fast_rcp(1.0f + __expf(2.0f * x));
}
// 64-long dot via LDS.128: wp = 32 packed f32x2, h = 64 floats (16B-aligned SMEM).
__device__ __forceinline__ float dot64v(const unsigned long long* wp, const float* h) {
    const ulonglong2* hp = reinterpret_cast<const ulonglong2*>(h);
    unsigned long long a0 = 0ULL, a1 = 0ULL, a2 = 0ULL, a3 = 0ULL;
#pragma unroll
    for (int j = 0; j < 16; j += 2) {
        ulonglong2 h01 = hp[j];
        ulonglong2 h23 = hp[j + 1];
        fma2(a0, wp[2 * j + 0], h01.x);
        fma2(a1, wp[2 * j + 1], h01.y);
        fma2(a2, wp[2 * j + 2], h23.x);
        fma2(a3, wp[2 * j + 3], h23.y);
    }
    float2 s0 = unpack2(a0), s1 = unpack2(a1), s2 = unpack2(a2), s3 = unpack2(a3);
    return (((s0.x + s0.y) + (s1.x + s1.y)) + ((s2.x + s2.y) + (s3.x + s3.y)));
}

// ---------------- cp.async helpers ----------------
static __device__ __forceinline__ uint32_t smem_u32(const void* p) {
    uint32_t a;
    asm("{ .reg .u64 t; cvta.to.shared.u64 t, %1; cvt.u32.u64 %0, t; }"
        : "=r"(a) : "l"(p));
    return a;
}
__device__ __forceinline__ void cp16(uint32_t dst, const void* src) {
    asm volatile("cp.async.cg.shared.global [%0], [%1], 16;"
                 :: "r"(dst), "l"(src));
}
__device__ __forceinline__ void cp_commit() {
    asm volatile("cp.async.commit_group;" ::: "memory");
}
template <int N>
__device__ __forceinline__ void cp_wait() {
    asm volatile("cp.async.wait_group %0;" :: "n"(N) : "memory");
}

// ---------------- generic C[M,N] = A[M,K] * B[N,K]^T + bias1 (+bias2) ----------------
__global__ void gemm_nt_bias(const float* __restrict__ A, const float* __restrict__ Bm,
                             const float* __restrict__ bias1, const float* __restrict__ bias2,
                             float* __restrict__ C, int M, int N, int K)
{
    __shared__ __align__(16) float As[64][17];
    __shared__ __align__(16) float Bs[16][68];

    const int t  = threadIdx.x;
    const int bm = blockIdx.y * 64;
    const int bn = blockIdx.x * 64;
    const int tm = (t >> 4) << 2;
    const int tn = (t & 15) << 2;
    const int lr = t >> 2;
    const int lk = (t & 3) << 2;

    unsigned long long acc[4][2];
#pragma unroll
    for (int i = 0; i < 4; i++) { acc[i][0] = 0ULL; acc[i][1] = 0ULL; }

    const float* Aptr = A  + (size_t)(bm + lr) * K + lk;
    const float* Bptr = Bm + (size_t)(bn + lr) * K + lk;

    for (int k0 = 0; k0 < K; k0 += 16) {
        float4 av = *reinterpret_cast<const float4*>(Aptr + k0);
        float4 bv = *reinterpret_cast<const float4*>(Bptr + k0);
        As[lr][lk + 0] = av.x; As[lr][lk + 1] = av.y;
        As[lr][lk + 2] = av.z; As[lr][lk + 3] = av.w;
        Bs[lk + 0][lr] = bv.x; Bs[lk + 1][lr] = bv.y;
        Bs[lk + 2][lr] = bv.z; Bs[lk + 3][lr] = bv.w;
        __syncthreads();
#pragma unroll
        for (int kk = 0; kk < 16; kk++) {
            unsigned long long b0 =
                *reinterpret_cast<const unsigned long long*>(&Bs[kk][tn]);
            unsigned long long b1 =
                *reinterpret_cast<const unsigned long long*>(&Bs[kk][tn + 2]);
#pragma unroll
            for (int i = 0; i < 4; i++) {
                unsigned long long ap = pack2(As[tm + i][kk]);
                fma2(acc[i][0], ap, b0);
                fma2(acc[i][1], ap, b1);
            }
        }
        __syncthreads();
    }

    float4 bvec;
    bvec.x = bias1[bn + tn + 0];
    bvec.y = bias1[bn + tn + 1];
    bvec.z = bias1[bn + tn + 2];
    bvec.w = bias1[bn + tn + 3];
    if (bias2) {
        bvec.x += bias2[bn + tn + 0];
        bvec.y += bias2[bn + tn + 1];
        bvec.z += bias2[bn + tn + 2];
        bvec.w += bias2[bn + tn + 3];
    }
#pragma unroll
    for (int i = 0; i < 4; i++) {
        float2 lo = unpack2(acc[i][0]);
        float2 hi = unpack2(acc[i][1]);
        float4 v = make_float4(lo.x + bvec.x, lo.y + bvec.y,
                               hi.x + bvec.z, hi.y + bvec.w);
        *reinterpret_cast<float4*>(&C[(size_t)(bm + tm + i) * N + bn + tn]) = v;
    }
}

// ============ LSTM recurrence (R12 form — best-known, closed) =======================
__global__ void __launch_bounds__(256, 1)
lstm_layer(const float* __restrict__ xproj,   // [B,T,256] incl. biases
           const float* __restrict__ Whh,     // [256,64]
           float* __restrict__ hout,          // [B,T,64] fp32 or null
           __half* __restrict__ ah_out)       // [B,T,64] fp16 or null
{
    __shared__ __align__(16) float h_sh[2][Hdim];

    const int b = blockIdx.x;
    const int tid = threadIdx.x;
    const int q = tid >> 2;          // h index 0..63
    const int k = tid & 3;           // gate type 0=i 1=f 2=g 3=o
    const int base = (tid & 31) & ~3;
    const int gidx = k * Hdim + q;   // weight row / xproj column

    unsigned long long wp[Hdim / 2];
#pragma unroll
    for (int j = 0; j < Hdim / 2; j++) {
        float2 v = *reinterpret_cast<const float2*>(Whh + gidx * Hdim + 2 * j);
        wp[j] = pack2v(v.x, v.y);
    }

    if (tid < Hdim) { h_sh[0][tid] = 0.0f; h_sh[1][tid] = 0.0f; }
    __syncthreads();

    const float* xp = xproj + (size_t)b * Tlen * Gdim;
    float xcur = xp[gidx];
    float c = 0.0f;

    for (int t = 0; t < Tlen; t++) {
        float xnext = (t + 1 < Tlen) ? xp[(size_t)(t + 1) * Gdim + gidx] : 0.0f;
        float val = xcur + dot64v(wp, h_sh[t & 1]);
        xcur = xnext;

        float act = (k == 2) ? tanh_fast(val) : sigmoidf_(val);

        float iv = __shfl_sync(0xffffffffu, act, base + 0);
        float fv = __shfl_sync(0xffffffffu, act, base + 1);
        float gv = __shfl_sync(0xffffffffu, act, base + 2);
        float ov = __shfl_sync(0xffffffffu, act, base + 3);

        c = fv * c + iv * gv;
        float hn = ov * tanh_fast(c);

        if (k == 0) {
            h_sh[(t + 1) & 1][q] = hn;
            size_t idx = ((size_t)b * Tlen + t) * Hdim + q;
            if (hout) hout[idx] = hn;
            if (ah_out) ah_out[idx] = __float2half(hn);
        }
        __syncthreads();
    }
}

// ---------------- Wl -> fp16 (scaled by 8 for fp16 normal range) -------
__global__ void cvt_bh(const float* __restrict__ in, __half* __restrict__ out, int n)
{
    int i = blockIdx.x * blockDim.x + threadIdx.x;
    if (i < n) out[i] = __float2half(in[i] * 8.0f);
}

// ============ HMMA fp16 logits GEMM: 64x64 CTA tile, 3 CTAs/SM ======================
// Same total MMA count & traffic as the 128x64 version; smaller SMEM footprint
// (B 8KB + 2 x 8KB A stages ~ 25KB) lifts occupancy 2 -> 3+ CTAs/SM to hide the
// L2/DRAM latency of the 512MB output stream.
// 8 warps: wm = wid&1 (32 rows), wn = wid>>1 (16 cols). Warp tile 32x16.
#define SWZ128(off) ((off) ^ (((off) >> 3) & 0x70))
#define LS_B    0
#define LS_A    8192
#define LS_ASTG 8192
#define LG_SMEM (8192 + 2 * 8192 + 1024)
#define NM_TILES 16            // m-tiles of 64 rows per CTA -> grid.y = 16

__device__ __forceinline__ void ldsm_x4(uint32_t& r0, uint32_t& r1, uint32_t& r2,
                                        uint32_t& r3, uint32_t addr) {
    asm volatile("ldmatrix.sync.aligned.m8n8.x4.shared.b16 {%0,%1,%2,%3}, [%4];"
                 : "=r"(r0), "=r"(r1), "=r"(r2), "=r"(r3) : "r"(addr));
}
__device__ __forceinline__ void mma_f16(float* c, uint32_t a0, uint32_t a1,
                                        uint32_t a2, uint32_t a3,
                                        uint32_t b0, uint32_t b1) {
    asm volatile("mma.sync.aligned.m16n8k16.row.col.f32.f16.f16.f32 "
                 "{%0,%1,%2,%3}, {%4,%5,%6,%7}, {%8,%9}, {%0,%1,%2,%3};"
                 : "+f"(c[0]), "+f"(c[1]), "+f"(c[2]), "+f"(c[3])
                 : "r"(a0), "r"(a1), "r"(a2), "r"(a3), "r"(b0), "r"(b1));
}
__device__ __forceinline__ void stg_cs_f2(float* p, float x, float y) {
    asm volatile("st.global.cs.v2.f32 [%0], {%1,%2};" :: "l"(p), "f"(x), "f"(y));
}

// Load one 64-row A m-tile (64 x 128B = 8KB): thread -> row tid/4, 2 chunks
__device__ __forceinline__ void load_A_stage64(uint32_t sA, const __half* Ah,
                                               int bm, int tid) {
    const int row = tid >> 2;            // 0..63
    const int cb = (tid & 3) * 2;        // chunks 0,2,4,6
    const char* src = reinterpret_cast<const char*>(Ah + (size_t)(bm + row) * Hdim);
#pragma unroll
    for (int i = 0; i < 2; i++) {
        uint32_t off = SWZ128((uint32_t)(row * 128 + (cb + i) * 16));
        cp16(sA + off, src + (cb + i) * 16);
    }
}

__global__ void __launch_bounds__(256, 3)
logits_gemm(const __half* __restrict__ Ah, const __half* __restrict__ Bh,
            const float* __restrict__ bias, float* __restrict__ C)
{
    extern __shared__ char smem_raw[];
    const uint32_t sb0 = smem_u32(smem_raw);
    const uint32_t sb = (sb0 + 1023) & ~1023u;

    const int tid = threadIdx.x;
    const int lane = tid & 31;
    const int wid = tid >> 5;
    const int wm = wid & 1;        // 0..1: 32-row half
    const int wn = wid >> 1;       // 0..3: 16-col slice
    const int bn = blockIdx.x * 64;
    const int bm0 = blockIdx.y * (NM_TILES * 64);

    // resident B tile (64 rows x 128B)
    {
        const int row = tid >> 2;
        const int cb = (tid & 3) * 2;
        const char* src = reinterpret_cast<const char*>(Bh + (size_t)(bn + row) * Hdim);
#pragma unroll
        for (int i = 0; i < 2; i++) {
            uint32_t off = SWZ128((uint32_t)(row * 128 + (cb + i) * 16));
            cp16(sb + LS_B + off, src + (cb + i) * 16);
        }
    }
    load_A_stage64(sb + LS_A, Ah, bm0, tid);
    cp_commit();

    const int gid = lane >> 2;
    const int tig = lane & 3;
    float2 bv[2];
#pragma unroll
    for (int nt = 0; nt < 2; nt++)
        bv[nt] = *reinterpret_cast<const float2*>(bias + bn + wn * 16 + nt * 8 + 2 * tig);

    const int rsel = lane & 15;
    const int csel = lane >> 4;

    for (int it = 0; it < NM_TILES; it++) {
        const uint32_t sA = sb + LS_A + (it & 1) * LS_ASTG;
        if (it + 1 < NM_TILES) {
            load_A_stage64(sb + LS_A + ((it + 1) & 1) * LS_ASTG, Ah,
                           bm0 + (it + 1) * 64, tid);
            cp_commit();
            cp_wait<1>();
        } else {
            cp_wait<0>();
        }
        __syncthreads();

        float acc[2][2][4];   // [mt][nt][frag]
#pragma unroll
        for (int i = 0; i < 2; i++)
#pragma unroll
            for (int j = 0; j < 2; j++)
#pragma unroll
                for (int f = 0; f < 4; f++) acc[i][j][f] = 0.0f;

#pragma unroll
        for (int ks = 0; ks < 4; ks++) {
            const int col16 = ks * 2 + csel;
            uint32_t a[2][4];
#pragma unroll
            for (int mt = 0; mt < 2; mt++) {
                int row = wm * 32 + mt * 16 + rsel;
                uint32_t addr = sA + SWZ128((uint32_t)(row * 128 + col16 * 16));
                ldsm_x4(a[mt][0], a[mt][1], a[mt][2], a[mt][3], addr);
            }
            // one B ldsm.x4 covers 16 rows -> both 8-col nt groups
            uint32_t b0[2], b1[2];
            {
                int row = wn * 16 + rsel;
                uint32_t addr = sb + LS_B + SWZ128((uint32_t)(row * 128 + col16 * 16));
                uint32_t r0, r1, r2, r3;
                ldsm_x4(r0, r1, r2, r3, addr);
                b0[0] = r0; b0[1] = r1;
                b1[0] = r2; b1[1] = r3;
            }
#pragma unroll
            for (int mt = 0; mt < 2; mt++)
#pragma unroll
                for (int nt = 0; nt < 2; nt++)
                    mma_f16(acc[mt][nt], a[mt][0], a[mt][1], a[mt][2], a[mt][3],
                            b0[nt], b1[nt]);
        }

        const int bm = bm0 + it * 64;
#pragma unroll
        for (int nt = 0; nt < 2; nt++) {
            const int gn = bn + wn * 16 + nt * 8 + 2 * tig;
#pragma unroll
            for (int mt = 0; mt < 2; mt++) {
                const int gm0 = bm + wm * 32 + mt * 16 + gid;
                float x0 = fmaf(acc[mt][nt][0], 0.125f, bv[nt].x);
                float y0 = fmaf(acc[mt][nt][1], 0.125f, bv[nt].y);
                float x1 = fmaf(acc[mt][nt][2], 0.125f, bv[nt].x);
                float y1 = fmaf(acc[mt][nt][3], 0.125f, bv[nt].y);
                stg_cs_f2(C + (size_t)gm0 * Vocab + gn, x0, y0);
                stg_cs_f2(C + (size_t)(gm0 + 8) * Vocab + gn, x1, y1);
            }
        }
        __syncthreads();
    }
}

// ------------------------------------ launch --------------------------------------
extern "C" void kernel_launch(void* const* d_in, const int* in_sizes, int n_in,
                              void* d_out, int out_size)
{
    (void)in_sizes; (void)n_in; (void)out_size;
    const float* x     = (const float*)d_in[0];
    const float* W_ih0 = (const float*)d_in[1];
    const float* W_hh0 = (const float*)d_in[2];
    const float* b_ih0 = (const float*)d_in[3];
    const float* b_hh0 = (const float*)d_in[4];
    const float* W_ih1 = (const float*)d_in[5];
    const float* W_hh1 = (const float*)d_in[6];
    const float* b_ih1 = (const float*)d_in[7];
    const float* b_hh1 = (const float*)d_in[8];
    const float* Wl    = (const float*)d_in[9];
    const float* bl    = (const float*)d_in[10];
    float* out = (float*)d_out;

    void* p;
    cudaGetSymbolAddress(&p, g_xproj); float* xproj = (float*)p;
    cudaGetSymbolAddress(&p, g_h1);    float* h1    = (float*)p;
    cudaGetSymbolAddress(&p, g_Ah);    __half* Ah   = (__half*)p;
    cudaGetSymbolAddress(&p, g_Bh);    __half* Bh   = (__half*)p;

    // Wl -> fp16 (independent of LSTM chain)
    cvt_bh<<<(Vocab * Hdim + 255) / 256, 256>>>(Wl, Bh, Vocab * Hdim);

    // Layer 0 input projection
    gemm_nt_bias<<<dim3(Gdim / 64, Mrows / 64), 256>>>(
        x, W_ih0, b_ih0, b_hh0, xproj, Mrows, Gdim, INSZ);
    // Layer 0 recurrence -> h1 (fp32)
    lstm_layer<<<Bsz, Gdim>>>(xproj, W_hh0, h1, nullptr);
    // Layer 1 input projection
    gemm_nt_bias<<<dim3(Gdim / 64, Mrows / 64), 256>>>(
        h1, W_ih1, b_ih1, b_hh1, xproj, Mrows, Gdim, Hdim);
    // Layer 1 recurrence -> fp16 A directly
    lstm_layer<<<Bsz, Gdim>>>(xproj, W_hh1, nullptr, Ah);

    // Logits: 64x64 CTA tiles, higher occupancy
    cudaFuncSetAttribute(logits_gemm, cudaFuncAttributeMaxDynamicSharedMemorySize, LG_SMEM);
    logits_gemm<<<dim3(Vocab / 64, Mrows / (NM_TILES * 64)), 256, LG_SMEM>>>(
        Ah, Bh, bl, out);
}

// round 17
// speedup vs baseline: 1.0559x; 1.0093x over previous
#include <cuda_runtime.h>
#include <cuda_fp16.h>
#include <cstdint>

// Problem constants
#define Bsz   64
#define Tlen  256
#define INSZ  256
#define Hdim  64
#define Gdim  256        // 4*Hdim
#define Vocab 8000
#define Mrows (Bsz * Tlen)   // 16384

// Scratch (device globals; no allocation allowed in kernel_launch)
__device__ float g_xproj[Mrows * Gdim];     // layer0 input projection
__device__ float g_xproj2[Mrows * Gdim];    // layer1 input projection (from lstm0)
__device__ __align__(128) __half g_Ah[Mrows * Hdim];    // h2 rounded to fp16
__device__ __align__(128) __half g_Bh[Vocab * Hdim];    // 8*Wl rounded to fp16

// ---------------- packed f32x2 helpers ----------------
__device__ __forceinline__ unsigned long long pack2(float x) {
    unsigned long long r;
    asm("mov.b64 %0, {%1, %1};" : "=l"(r) : "f"(x));
    return r;
}
__device__ __forceinline__ unsigned long long pack2v(float x, float y) {
    unsigned long long r;
    asm("mov.b64 %0, {%1, %2};" : "=l"(r) : "f"(x), "f"(y));
    return r;
}
__device__ __forceinline__ void fma2(unsigned long long& d, unsigned long long a,
                                     unsigned long long b) {
    asm("fma.rn.f32x2 %0, %1, %2, %0;" : "+l"(d) : "l"(a), "l"(b));
}
__device__ __forceinline__ float2 unpack2(unsigned long long v) {
    float2 f;
    asm("mov.b64 {%0, %1}, %2;" : "=f"(f.x), "=f"(f.y) : "l"(v));
    return f;
}
__device__ __forceinline__ float fast_rcp(float x) {
    float r;
    asm("rcp.approx.f32 %0, %1;" : "=f"(r) : "f"(x));
    return r;
}
__device__ __forceinline__ float sigmoidf_(float x) {
    return fast_rcp(1.0f + __expf(-x));
}
__device__ __forceinline__ float tanh_fast(float x) {
    return 1.0f - 2.0f * fast_rcp(1.0f + __expf(2.0f * x));
}
// 64-long dot via LDS.128: wp = 32 packed f32x2, h = 64 floats (16B-aligned SMEM).
__device__ __forceinline__ float dot64v(const unsigned long long* wp, const float* h) {
    const ulonglong2* hp = reinterpret_cast<const ulonglong2*>(h);
    unsigned long long a0 = 0ULL, a1 = 0ULL, a2 = 0ULL, a3 = 0ULL;
#pragma unroll
    for (int j = 0; j < 16; j += 2) {
        ulonglong2 h01 = hp[j];
        ulonglong2 h23 = hp[j + 1];
        fma2(a0, wp[2 * j + 0], h01.x);
        fma2(a1, wp[2 * j + 1], h01.y);
        fma2(a2, wp[2 * j + 2], h23.x);
        fma2(a3, wp[2 * j + 3], h23.y);
    }
    float2 s0 = unpack2(a0), s1 = unpack2(a1), s2 = unpack2(a2), s3 = unpack2(a3);
    return (((s0.x + s0.y) + (s1.x + s1.y)) + ((s2.x + s2.y) + (s3.x + s3.y)));
}
// Dual 64-long dot sharing one set of h loads (R14-proven: zero pace cost).
__device__ __forceinline__ float2 dot64v2(const unsigned long long* wa,
                                          const unsigned long long* wb,
                                          const float* h) {
    const ulonglong2* hp = reinterpret_cast<const ulonglong2*>(h);
    unsigned long long a0 = 0ULL, a1 = 0ULL, a2 = 0ULL, a3 = 0ULL;
    unsigned long long b0 = 0ULL, b1 = 0ULL, b2 = 0ULL, b3 = 0ULL;
#pragma unroll
    for (int j = 0; j < 16; j += 2) {
        ulonglong2 h01 = hp[j];
        ulonglong2 h23 = hp[j + 1];
        fma2(a0, wa[2 * j + 0], h01.x);  fma2(b0, wb[2 * j + 0], h01.x);
        fma2(a1, wa[2 * j + 1], h01.y);  fma2(b1, wb[2 * j + 1], h01.y);
        fma2(a2, wa[2 * j + 2], h23.x);  fma2(b2, wb[2 * j + 2], h23.x);
        fma2(a3, wa[2 * j + 3], h23.y);  fma2(b3, wb[2 * j + 3], h23.y);
    }
    float2 s0 = unpack2(a0), s1 = unpack2(a1), s2 = unpack2(a2), s3 = unpack2(a3);
    float2 t0 = unpack2(b0), t1 = unpack2(b1), t2 = unpack2(b2), t3 = unpack2(b3);
    float2 r;
    r.x = (((s0.x + s0.y) + (s1.x + s1.y)) + ((s2.x + s2.y) + (s3.x + s3.y)));
    r.y = (((t0.x + t0.y) + (t1.x + t1.y)) + ((t2.x + t2.y) + (t3.x + t3.y)));
    return r;
}

// ---------------- cp.async helpers ----------------
static __device__ __forceinline__ uint32_t smem_u32(const void* p) {
    uint32_t a;
    asm("{ .reg .u64 t; cvta.to.shared.u64 t, %1; cvt.u32.u64 %0, t; }"
        : "=r"(a) : "l"(p));
    return a;
}
__device__ __forceinline__ void cp16(uint32_t dst, const void* src) {
    asm volatile("cp.async.cg.shared.global [%0], [%1], 16;"
                 :: "r"(dst), "l"(src));
}
__device__ __forceinline__ void cp_commit() {
    asm volatile("cp.async.commit_group;" ::: "memory");
}
template <int N>
__device__ __forceinline__ void cp_wait() {
    asm volatile("cp.async.wait_group %0;" :: "n"(N) : "memory");
}

// ---------------- generic C[M,N] = A[M,K] * B[N,K]^T + bias1 (+bias2) ----------------
__global__ void gemm_nt_bias(const float* __restrict__ A, const float* __restrict__ Bm,
                             const float* __restrict__ bias1, const float* __restrict__ bias2,
                             float* __restrict__ C, int M, int N, int K)
{
    __shared__ __align__(16) float As[64][17];
    __shared__ __align__(16) float Bs[16][68];

    const int t  = threadIdx.x;
    const int bm = blockIdx.y * 64;
    const int bn = blockIdx.x * 64;
    const int tm = (t >> 4) << 2;
    const int tn = (t & 15) << 2;
    const int lr = t >> 2;
    const int lk = (t & 3) << 2;

    unsigned long long acc[4][2];
#pragma unroll
    for (int i = 0; i < 4; i++) { acc[i][0] = 0ULL; acc[i][1] = 0ULL; }

    const float* Aptr = A  + (size_t)(bm + lr) * K + lk;
    const float* Bptr = Bm + (size_t)(bn + lr) * K + lk;

    for (int k0 = 0; k0 < K; k0 += 16) {
        float4 av = *reinterpret_cast<const float4*>(Aptr + k0);
        float4 bv = *reinterpret_cast<const float4*>(Bptr + k0);
        As[lr][lk + 0] = av.x; As[lr][lk + 1] = av.y;
        As[lr][lk + 2] = av.z; As[lr][lk + 3] = av.w;
        Bs[lk + 0][lr] = bv.x; Bs[lk + 1][lr] = bv.y;
        Bs[lk + 2][lr] = bv.z; Bs[lk + 3][lr] = bv.w;
        __syncthreads();
#pragma unroll
        for (int kk = 0; kk < 16; kk++) {
            unsigned long long b0 =
                *reinterpret_cast<const unsigned long long*>(&Bs[kk][tn]);
            unsigned long long b1 =
                *reinterpret_cast<const unsigned long long*>(&Bs[kk][tn + 2]);
#pragma unroll
            for (int i = 0; i < 4; i++) {
                unsigned long long ap = pack2(As[tm + i][kk]);
                fma2(acc[i][0], ap, b0);
                fma2(acc[i][1], ap, b1);
            }
        }
        __syncthreads();
    }

    float4 bvec;
    bvec.x = bias1[bn + tn + 0];
    bvec.y = bias1[bn + tn + 1];
    bvec.z = bias1[bn + tn + 2];
    bvec.w = bias1[bn + tn + 3];
    if (bias2) {
        bvec.x += bias2[bn + tn + 0];
        bvec.y += bias2[bn + tn + 1];
        bvec.z += bias2[bn + tn + 2];
        bvec.w += bias2[bn + tn + 3];
    }
#pragma unroll
    for (int i = 0; i < 4; i++) {
        float2 lo = unpack2(acc[i][0]);
        float2 hi = unpack2(acc[i][1]);
        float4 v = make_float4(lo.x + bvec.x, lo.y + bvec.y,
                               hi.x + bvec.z, hi.y + bvec.w);
        *reinterpret_cast<float4*>(&C[(size_t)(bm + tm + i) * N + bn + tn]) = v;
    }
}

// ============ Layer-0 LSTM with fused layer-1 input projection ======================
// R12 recurrence form + dual dot: at step t the shared h vector (= h0[t-1]) feeds
// both the layer0 gate dot AND pih[t-1] = W_ih1 @ h0[t-1] (+ layer1 biases),
// streamed to xproj2. Eliminates the proj1 GEMM and the h1 fp32 round-trip.
__global__ void __launch_bounds__(256, 1)
lstm_layer0(const float* __restrict__ xproj,   // [B,T,256] incl. layer0 biases
            const float* __restrict__ Whh0,    // [256,64]
            const float* __restrict__ Wih1,    // [256,64]
            const float* __restrict__ bih1,    // [256]
            const float* __restrict__ bhh1,    // [256]
            float* __restrict__ xproj2)        // [B,T,256] out: pih + biases
{
    __shared__ __align__(16) float h_sh[2][Hdim];

    const int b = blockIdx.x;
    const int tid = threadIdx.x;
    const int q = tid >> 2;
    const int k = tid & 3;
    const int base = (tid & 31) & ~3;
    const int gidx = k * Hdim + q;

    unsigned long long wp[Hdim / 2], wih[Hdim / 2];
#pragma unroll
    for (int j = 0; j < Hdim / 2; j++) {
        float2 v = *reinterpret_cast<const float2*>(Whh0 + gidx * Hdim + 2 * j);
        float2 u = *reinterpret_cast<const float2*>(Wih1 + gidx * Hdim + 2 * j);
        wp[j] = pack2v(v.x, v.y);
        wih[j] = pack2v(u.x, u.y);
    }
    const float bias1 = bih1[gidx] + bhh1[gidx];

    if (tid < Hdim) { h_sh[0][tid] = 0.0f; h_sh[1][tid] = 0.0f; }
    __syncthreads();

    const float* xp = xproj + (size_t)b * Tlen * Gdim;
    float* xp2 = xproj2 + (size_t)b * Tlen * Gdim;
    float xcur = xp[gidx];
    float c = 0.0f;

    for (int t = 0; t < Tlen; t++) {
        float xnext = (t + 1 < Tlen) ? xp[(size_t)(t + 1) * Gdim + gidx] : 0.0f;
        float2 d = dot64v2(wp, wih, h_sh[t & 1]);   // d.x: gate dot, d.y: pih[t-1]
        float val = xcur + d.x;
        xcur = xnext;
        if (t >= 1) xp2[(size_t)(t - 1) * Gdim + gidx] = d.y + bias1;

        float act = (k == 2) ? tanh_fast(val) : sigmoidf_(val);

        float iv = __shfl_sync(0xffffffffu, act, base + 0);
        float fv = __shfl_sync(0xffffffffu, act, base + 1);
        float gv = __shfl_sync(0xffffffffu, act, base + 2);
        float ov = __shfl_sync(0xffffffffu, act, base + 3);

        c = fv * c + iv * gv;
        float hn = ov * tanh_fast(c);

        if (k == 0) h_sh[(t + 1) & 1][q] = hn;
        __syncthreads();
    }
    // pih for the last step: h_sh[Tlen & 1] holds h0[Tlen-1]
    xp2[(size_t)(Tlen - 1) * Gdim + gidx] =
        dot64v(wih, h_sh[Tlen & 1]) + bias1;
}

// ============ Layer-1 LSTM recurrence (R12 form, reads fused pih) ===================
__global__ void __launch_bounds__(256, 1)
lstm_layer1(const float* __restrict__ xproj,   // [B,T,256] pih incl. biases
            const float* __restrict__ Whh,     // [256,64]
            __half* __restrict__ ah_out)       // [B,T,64] fp16
{
    __shared__ __align__(16) float h_sh[2][Hdim];

    const int b = blockIdx.x;
    const int tid = threadIdx.x;
    const int q = tid >> 2;
    const int k = tid & 3;
    const int base = (tid & 31) & ~3;
    const int gidx = k * Hdim + q;

    unsigned long long wp[Hdim / 2];
#pragma unroll
    for (int j = 0; j < Hdim / 2; j++) {
        float2 v = *reinterpret_cast<const float2*>(Whh + gidx * Hdim + 2 * j);
        wp[j] = pack2v(v.x, v.y);
    }

    if (tid < Hdim) { h_sh[0][tid] = 0.0f; h_sh[1][tid] = 0.0f; }
    __syncthreads();

    const float* xp = xproj + (size_t)b * Tlen * Gdim;
    float xcur = xp[gidx];
    float c = 0.0f;

    for (int t = 0; t < Tlen; t++) {
        float xnext = (t + 1 < Tlen) ? xp[(size_t)(t + 1) * Gdim + gidx] : 0.0f;
        float val = xcur + dot64v(wp, h_sh[t & 1]);
        xcur = xnext;

        float act = (k == 2) ? tanh_fast(val) : sigmoidf_(val);

        float iv = __shfl_sync(0xffffffffu, act, base + 0);
        float fv = __shfl_sync(0xffffffffu, act, base + 1);
        float gv = __shfl_sync(0xffffffffu, act, base + 2);
        float ov = __shfl_sync(0xffffffffu, act, base + 3);

        c = fv * c + iv * gv;
        float hn = ov * tanh_fast(c);

        if (k == 0) {
            h_sh[(t + 1) & 1][q] = hn;
            ah_out[((size_t)b * Tlen + t) * Hdim + q] = __float2half(hn);
        }
        __syncthreads();
    }
}

// ---------------- Wl -> fp16 (scaled by 8 for fp16 normal range) -------
__global__ void cvt_bh(const float* __restrict__ in, __half* __restrict__ out, int n)
{
    int i = blockIdx.x * blockDim.x + threadIdx.x;
    if (i < n) out[i] = __float2half(in[i] * 8.0f);
}

// ============ HMMA fp16 logits GEMM (byte-identical to the 442.9us best) ============
#define SWZ128(off) ((off) ^ (((off) >> 3) & 0x70))
#define LS_B    0
#define LS_A    8192
#define LS_ASTG 16384
#define LG_SMEM (8192 + 2 * 16384 + 1024)
#define NM_TILES 8

__device__ __forceinline__ void ldsm_x4(uint32_t& r0, uint32_t& r1, uint32_t& r2,
                                        uint32_t& r3, uint32_t addr) {
    asm volatile("ldmatrix.sync.aligned.m8n8.x4.shared.b16 {%0,%1,%2,%3}, [%4];"
                 : "=r"(r0), "=r"(r1), "=r"(r2), "=r"(r3) : "r"(addr));
}
__device__ __forceinline__ void mma_f16(float* c, uint32_t a0, uint32_t a1,
                                        uint32_t a2, uint32_t a3,
                                        uint32_t b0, uint32_t b1) {
    asm volatile("mma.sync.aligned.m16n8k16.row.col.f32.f16.f16.f32 "
                 "{%0,%1,%2,%3}, {%4,%5,%6,%7}, {%8,%9}, {%0,%1,%2,%3};"
                 : "+f"(c[0]), "+f"(c[1]), "+f"(c[2]), "+f"(c[3])
                 : "r"(a0), "r"(a1), "r"(a2), "r"(a3), "r"(b0), "r"(b1));
}
__device__ __forceinline__ void stg_cs_f2(float* p, float x, float y) {
    asm volatile("st.global.cs.v2.f32 [%0], {%1,%2};" :: "l"(p), "f"(x), "f"(y));
}

__device__ __forceinline__ void load_A_stage(uint32_t sA, const __half* Ah,
                                             int bm, int tid) {
    const int row = tid >> 1;
    const int cb = (tid & 1) * 4;
    const char* src = reinterpret_cast<const char*>(Ah + (size_t)(bm + row) * Hdim);
#pragma unroll
    for (int i = 0; i < 4; i++) {
        uint32_t off = SWZ128((uint32_t)(row * 128 + (cb + i) * 16));
        cp16(sA + off, src + (cb + i) * 16);
    }
}

__global__ void __launch_bounds__(256)
logits_gemm(const __half* __restrict__ Ah, const __half* __restrict__ Bh,
            const float* __restrict__ bias, float* __restrict__ C)
{
    extern __shared__ char smem_raw[];
    const uint32_t sb0 = smem_u32(smem_raw);
    const uint32_t sb = (sb0 + 1023) & ~1023u;

    const int tid = threadIdx.x;
    const int lane = tid & 31;
    const int wid = tid >> 5;
    const int wm = wid & 3;
    const int wn = wid >> 2;
    const int bn = blockIdx.x * 64;
    const int bm0 = blockIdx.y * (NM_TILES * 128);

    {
        const int row = tid >> 2;
        const int cb = (tid & 3) * 2;
        const char* src = reinterpret_cast<const char*>(Bh + (size_t)(bn + row) * Hdim);
#pragma unroll
        for (int i = 0; i < 2; i++) {
            uint32_t off = SWZ128((uint32_t)(row * 128 + (cb + i) * 16));
            cp16(sb + LS_B + off, src + (cb + i) * 16);
        }
    }
    load_A_stage(sb + LS_A, Ah, bm0, tid);
    cp_commit();

    const int gid = lane >> 2;
    const int tig = lane & 3;
    float2 bv[4];
#pragma unroll
    for (int nt = 0; nt < 4; nt++)
        bv[nt] = *reinterpret_cast<const float2*>(bias + bn + wn * 32 + nt * 8 + 2 * tig);

    const int rsel = lane & 15;
    const int csel = lane >> 4;

    for (int it = 0; it < NM_TILES; it++) {
        const uint32_t sA = sb + LS_A + (it & 1) * LS_ASTG;
        if (it + 1 < NM_TILES) {
            load_A_stage(sb + LS_A + ((it + 1) & 1) * LS_ASTG, Ah,
                         bm0 + (it + 1) * 128, tid);
            cp_commit();
            cp_wait<1>();
        } else {
            cp_wait<0>();
        }
        __syncthreads();

        float acc[2][4][4];
#pragma unroll
        for (int i = 0; i < 2; i++)
#pragma unroll
            for (int j = 0; j < 4; j++)
#pragma unroll
                for (int q = 0; q < 4; q++) acc[i][j][q] = 0.0f;

#pragma unroll
        for (int ks = 0; ks < 4; ks++) {
            const int col16 = ks * 2 + csel;
            uint32_t a[2][4];
#pragma unroll
            for (int mt = 0; mt < 2; mt++) {
                int row = wm * 32 + mt * 16 + rsel;
                uint32_t addr = sA + SWZ128((uint32_t)(row * 128 + col16 * 16));
                ldsm_x4(a[mt][0], a[mt][1], a[mt][2], a[mt][3], addr);
            }
            uint32_t b0[4], b1[4];
#pragma unroll
            for (int np = 0; np < 2; np++) {
                int row = wn * 32 + np * 16 + rsel;
                uint32_t addr = sb + LS_B + SWZ128((uint32_t)(row * 128 + col16 * 16));
                uint32_t r0, r1, r2, r3;
                ldsm_x4(r0, r1, r2, r3, addr);
                b0[np * 2 + 0] = r0; b0[np * 2 + 1] = r1;
                b1[np * 2 + 0] = r2; b1[np * 2 + 1] = r3;
            }
#pragma unroll
            for (int mt = 0; mt < 2; mt++)
#pragma unroll
                for (int nt = 0; nt < 4; nt++)
                    mma_f16(acc[mt][nt], a[mt][0], a[mt][1], a[mt][2], a[mt][3],
                            b0[nt], b1[nt]);
        }

        const int bm = bm0 + it * 128;
#pragma unroll
        for (int nt = 0; nt < 4; nt++) {
            const int gn = bn + wn * 32 + nt * 8 + 2 * tig;
#pragma unroll
            for (int mt = 0; mt < 2; mt++) {
                const int gm0 = bm + wm * 32 + mt * 16 + gid;
                float x0 = fmaf(acc[mt][nt][0], 0.125f, bv[nt].x);
                float y0 = fmaf(acc[mt][nt][1], 0.125f, bv[nt].y);
                float x1 = fmaf(acc[mt][nt][2], 0.125f, bv[nt].x);
                float y1 = fmaf(acc[mt][nt][3], 0.125f, bv[nt].y);
                stg_cs_f2(C + (size_t)gm0 * Vocab + gn, x0, y0);
                stg_cs_f2(C + (size_t)(gm0 + 8) * Vocab + gn, x1, y1);
            }
        }
        __syncthreads();
    }
}

// ------------------------------------ launch --------------------------------------
extern "C" void kernel_launch(void* const* d_in, const int* in_sizes, int n_in,
                              void* d_out, int out_size)
{
    (void)in_sizes; (void)n_in; (void)out_size;
    const float* x     = (const float*)d_in[0];
    const float* W_ih0 = (const float*)d_in[1];
    const float* W_hh0 = (const float*)d_in[2];
    const float* b_ih0 = (const float*)d_in[3];
    const float* b_hh0 = (const float*)d_in[4];
    const float* W_ih1 = (const float*)d_in[5];
    const float* W_hh1 = (const float*)d_in[6];
    const float* b_ih1 = (const float*)d_in[7];
    const float* b_hh1 = (const float*)d_in[8];
    const float* Wl    = (const float*)d_in[9];
    const float* bl    = (const float*)d_in[10];
    float* out = (float*)d_out;

    void* p;
    cudaGetSymbolAddress(&p, g_xproj);  float* xproj  = (float*)p;
    cudaGetSymbolAddress(&p, g_xproj2); float* xproj2 = (float*)p;
    cudaGetSymbolAddress(&p, g_Ah);     __half* Ah    = (__half*)p;
    cudaGetSymbolAddress(&p, g_Bh);     __half* Bh    = (__half*)p;

    // Wl -> fp16 (independent of LSTM chain)
    cvt_bh<<<(Vocab * Hdim + 255) / 256, 256>>>(Wl, Bh, Vocab * Hdim);

    // Layer 0 input projection (layer0 biases folded in)
    gemm_nt_bias<<<dim3(Gdim / 64, Mrows / 64), 256>>>(
        x, W_ih0, b_ih0, b_hh0, xproj, Mrows, Gdim, INSZ);

    // Layer 0 recurrence, fused layer-1 input projection -> xproj2
    lstm_layer0<<<Bsz, Gdim>>>(xproj, W_hh0, W_ih1, b_ih1, b_hh1, xproj2);

    // Layer 1 recurrence -> fp16 A directly
    lstm_layer1<<<Bsz, Gdim>>>(xproj2, W_hh1, Ah);

    // Logits via pipelined HMMA fp16 single pass
    cudaFuncSetAttribute(logits_gemm, cudaFuncAttributeMaxDynamicSharedMemorySize, LG_SMEM);
    logits_gemm<<<dim3(Vocab / 64, Mrows / (NM_TILES * 128)), 256, LG_SMEM>>>(
        Ah, Bh, bl, out);
}